// round 2
// baseline (speedup 1.0000x reference)
#include <cuda_runtime.h>

#define Bv 32
#define Tv 1500
#define Ev 1024
#define Hv 8
#define DKv 128
#define DVv 128
#define Dv 1024
#define SCALING 0.088388347648318447f  // 1/sqrt(128)

// Scratch (no allocations allowed)
__device__ float g_q[Bv * Hv * DKv];   // tanh(dec_z@Wq + bq)
__device__ float g_u[Bv * Hv * Ev];    // sum_t w * enc
__device__ float g_c[Bv * Hv * DVv];   // u @ Wv

// ---------------------------------------------------------------------------
// Length read with dtype sniff: reference declares int64 but JAX without x64
// emits int32. If genuinely int64 (LE, values in [750,1500]), word 1 is the
// zero high-word of lens[0]; if int32, word 1 is a length >= 750 != 0.
// ---------------------------------------------------------------------------
__device__ __forceinline__ int get_len(const int* __restrict__ L, int b) {
    bool is64 = (L[1] == 0);
    return is64 ? L[2 * b] : L[b];
}

// ---------------------------------------------------------------------------
// q[b,h,k] = tanh(dec_z[b,:]·Wq[h,:,k] + bq[h,k])
// ---------------------------------------------------------------------------
__global__ __launch_bounds__(128) void q_kernel(const float* __restrict__ dec_z,
                                                const float* __restrict__ Wq,
                                                const float* __restrict__ bq) {
    int h = blockIdx.x, b = blockIdx.y;
    int k = threadIdx.x;
    __shared__ float zs[Dv];
    for (int i = k; i < Dv; i += 128) zs[i] = dec_z[b * Dv + i];
    __syncthreads();
    float acc = bq[h * DKv + k];
    const float* W = Wq + (size_t)h * Dv * DKv + k;
#pragma unroll 8
    for (int d = 0; d < Dv; d++) acc += zs[d] * W[(size_t)d * DKv];
    g_q[(b * Hv + h) * DKv + k] = tanhf(acc);
}

// ---------------------------------------------------------------------------
// e[b,h,t] = sum_k tanh(enc[b,t,:]·Wk[h,:,k]) * q[b,h,k]
// Fused GEMM (128x128 tile, K-step 16, 8x8 micro-tile) + tanh + q-dot epilogue.
// Writes raw logits into the w output region (softmaxed in place later).
// ---------------------------------------------------------------------------
#define TM 128
#define TKs 16

__global__ __launch_bounds__(256, 2) void e_kernel(const float* __restrict__ enc,
                                                   const float* __restrict__ Wk,
                                                   float* __restrict__ ebuf) {
    int h = blockIdx.x, tile = blockIdx.y, b = blockIdx.z;
    int t0 = tile * TM;

    __shared__ __align__(16) float As[TKs][TM + 4];  // transposed A tile
    __shared__ __align__(16) float Bs[TKs][DKv];
    __shared__ float qs[DKv];
    __shared__ float red[TM][17];

    int tid = threadIdx.x;
    int ty = tid >> 4, tx = tid & 15;  // 16x16 thread grid, 8x8 outputs each

    if (tid < DKv) qs[tid] = g_q[(b * Hv + h) * DKv + tid];

    float acc[8][8];
#pragma unroll
    for (int i = 0; i < 8; i++)
#pragma unroll
        for (int j = 0; j < 8; j++) acc[i][j] = 0.f;

    const float* A = enc + (size_t)b * Tv * Ev;
    const float* W = Wk + (size_t)h * Ev * DKv;

    for (int k0 = 0; k0 < Ev; k0 += TKs) {
        // A tile: 128 rows x 16 cols -> 512 float4, 2 per thread (transpose into As)
#pragma unroll
        for (int r = 0; r < 2; r++) {
            int idx = r * 256 + tid;
            int row = idx >> 2;
            int seg = idx & 3;
            int t = t0 + row;
            float4 v = make_float4(0.f, 0.f, 0.f, 0.f);
            if (t < Tv) v = *(const float4*)(A + (size_t)t * Ev + k0 + seg * 4);
            As[seg * 4 + 0][row] = v.x;
            As[seg * 4 + 1][row] = v.y;
            As[seg * 4 + 2][row] = v.z;
            As[seg * 4 + 3][row] = v.w;
        }
        // B tile: 16 rows x 128 cols -> 512 float4, 2 per thread
#pragma unroll
        for (int r = 0; r < 2; r++) {
            int idx = r * 256 + tid;
            int row = idx >> 5;
            int c4 = idx & 31;
            *(float4*)&Bs[row][c4 * 4] =
                *(const float4*)(W + (size_t)(k0 + row) * DKv + c4 * 4);
        }
        __syncthreads();
#pragma unroll
        for (int kk = 0; kk < TKs; kk++) {
            float a[8], bb[8];
            float4 a0 = *(const float4*)&As[kk][ty * 8];
            float4 a1 = *(const float4*)&As[kk][ty * 8 + 4];
            a[0] = a0.x; a[1] = a0.y; a[2] = a0.z; a[3] = a0.w;
            a[4] = a1.x; a[5] = a1.y; a[6] = a1.z; a[7] = a1.w;
#pragma unroll
            for (int j = 0; j < 8; j++) bb[j] = Bs[kk][tx + 16 * j];
#pragma unroll
            for (int i = 0; i < 8; i++)
#pragma unroll
                for (int j = 0; j < 8; j++) acc[i][j] += a[i] * bb[j];
        }
        __syncthreads();
    }

    // Epilogue: tanh, dot with q, deterministic cross-tx reduction
#pragma unroll
    for (int i = 0; i < 8; i++) {
        float p = 0.f;
#pragma unroll
        for (int j = 0; j < 8; j++) p += tanhf(acc[i][j]) * qs[tx + 16 * j];
        red[ty * 8 + i][tx] = p;
    }
    __syncthreads();
    if (tid < TM) {
        int t = t0 + tid;
        if (t < Tv) {
            float s = 0.f;
#pragma unroll
            for (int j = 0; j < 16; j++) s += red[tid][j];
            ebuf[((size_t)(b * Hv + h)) * Tv + t] = s;
        }
    }
}

// ---------------------------------------------------------------------------
// Masked softmax over T, in place in the w output region.
// w = softmax(SCALING * e) over t < len, 0 elsewhere.
// ---------------------------------------------------------------------------
__global__ __launch_bounds__(256) void softmax_kernel(float* __restrict__ wbuf,
                                                      const int* __restrict__ lens) {
    int bh = blockIdx.x;
    int b = bh / Hv;
    int len = get_len(lens, b);
    int tid = threadIdx.x;
    __shared__ float s[Tv];
    __shared__ float red[16];
    float* row = wbuf + (size_t)bh * Tv;
    for (int t = tid; t < Tv; t += 256) s[t] = row[t];
    __syncthreads();

    // max of logits over valid range
    float m = -1e30f;
    for (int t = tid; t < len; t += 256) m = fmaxf(m, s[t]);
#pragma unroll
    for (int o = 16; o; o >>= 1) m = fmaxf(m, __shfl_xor_sync(0xffffffffu, m, o));
    if ((tid & 31) == 0) red[tid >> 5] = m;
    __syncthreads();
    m = red[0];
#pragma unroll
    for (int i = 1; i < 8; i++) m = fmaxf(m, red[i]);
    float M = SCALING * m;

    // sum of exp
    float lsum = 0.f;
    for (int t = tid; t < len; t += 256) lsum += expf(SCALING * s[t] - M);
#pragma unroll
    for (int o = 16; o; o >>= 1) lsum += __shfl_xor_sync(0xffffffffu, lsum, o);
    if ((tid & 31) == 0) red[8 + (tid >> 5)] = lsum;
    __syncthreads();
    float total = 0.f;
#pragma unroll
    for (int i = 0; i < 8; i++) total += red[8 + i];
    float inv = 1.f / total;

    for (int t = tid; t < Tv; t += 256)
        row[t] = (t < len) ? expf(SCALING * s[t] - M) * inv : 0.f;
}

// ---------------------------------------------------------------------------
// u[b,h,d] = sum_t w[b,h,t] * enc[b,t,d]   (folds away the 100 GF V GEMM)
// ---------------------------------------------------------------------------
__global__ __launch_bounds__(256) void u_kernel(const float* __restrict__ enc,
                                                const float* __restrict__ wbuf) {
    int chunk = blockIdx.x, b = blockIdx.y;
    int d = chunk * 256 + threadIdx.x;
    __shared__ float ws[Hv][128];
    float acc[Hv] = {0.f, 0.f, 0.f, 0.f, 0.f, 0.f, 0.f, 0.f};
    const float* A = enc + (size_t)b * Tv * Ev;
    for (int t0 = 0; t0 < Tv; t0 += 128) {
        __syncthreads();
#pragma unroll
        for (int r = 0; r < 4; r++) {
            int f = r * 256 + threadIdx.x;  // 0..1023
            int h = f >> 7, tt = f & 127;
            int t = t0 + tt;
            ws[h][tt] = (t < Tv) ? wbuf[((size_t)(b * Hv + h)) * Tv + t] : 0.f;
        }
        __syncthreads();
        int tmax = min(128, Tv - t0);
        for (int tt = 0; tt < tmax; tt++) {
            float x = A[(size_t)(t0 + tt) * Ev + d];
#pragma unroll
            for (int h = 0; h < Hv; h++) acc[h] += ws[h][tt] * x;
        }
    }
#pragma unroll
    for (int h = 0; h < Hv; h++) g_u[((size_t)(b * Hv + h)) * Ev + d] = acc[h];
}

// ---------------------------------------------------------------------------
// c[b,h,v] = u[b,h,:]·Wv[h,:,v]
// ---------------------------------------------------------------------------
__global__ __launch_bounds__(128) void c_kernel(const float* __restrict__ Wv) {
    int h = blockIdx.x, b = blockIdx.y;
    int v = threadIdx.x;
    __shared__ float us[Ev];
    for (int i = v; i < Ev; i += 128) us[i] = g_u[((size_t)(b * Hv + h)) * Ev + i];
    __syncthreads();
    float acc = 0.f;
    const float* W = Wv + (size_t)h * Ev * DVv + v;
#pragma unroll 8
    for (int d = 0; d < Ev; d++) acc += us[d] * W[(size_t)d * DVv];
    g_c[(b * Hv + h) * DVv + v] = acc;
}

// ---------------------------------------------------------------------------
// out[b,e] = c_flat[b,:]·Wo[:,e]
// ---------------------------------------------------------------------------
__global__ __launch_bounds__(256) void out_kernel(const float* __restrict__ Wo,
                                                  float* __restrict__ out) {
    int chunk = blockIdx.x, b = blockIdx.y;
    int e = chunk * 256 + threadIdx.x;
    __shared__ float cs[Hv * DVv];
    for (int i = threadIdx.x; i < Hv * DVv; i += 256) cs[i] = g_c[b * Hv * DVv + i];
    __syncthreads();
    float acc = 0.f;
#pragma unroll 8
    for (int i = 0; i < Hv * DVv; i++) acc += cs[i] * Wo[(size_t)i * Ev + e];
    out[(size_t)b * Ev + e] = acc;
}

// ---------------------------------------------------------------------------
extern "C" void kernel_launch(void* const* d_in, const int* in_sizes, int n_in,
                              void* d_out, int out_size) {
    const float* enc       = (const float*)d_in[0];       // (B,T,E)
    const int*   lens      = (const int*)d_in[1];         // (B,) int32 (or int64; sniffed)
    const float* dec_z     = (const float*)d_in[2];       // (B,D)
    const float* Wq        = (const float*)d_in[3];       // (H,D,DK)
    const float* bq        = (const float*)d_in[4];       // (H,DK)
    const float* Wk        = (const float*)d_in[5];       // (H,E,DK)
    const float* Wv        = (const float*)d_in[6];       // (H,E,DV)
    const float* Wo        = (const float*)d_in[7];       // (H*DV,E)

    float* out  = (float*)d_out;            // (B,E)
    float* wbuf = out + Bv * Ev;            // (B,H,T) — e logits, then w in place

    q_kernel<<<dim3(Hv, Bv), 128>>>(dec_z, Wq, bq);
    e_kernel<<<dim3(Hv, (Tv + TM - 1) / TM, Bv), 256>>>(enc, Wk, wbuf);
    softmax_kernel<<<Bv * Hv, 256>>>(wbuf, lens);
    u_kernel<<<dim3(Ev / 256, Bv), 256>>>(enc, wbuf);
    c_kernel<<<dim3(Hv, Bv), 128>>>(Wv);
    out_kernel<<<dim3(Ev / 256, Bv), 256>>>(Wo, out);
}

// round 4
// speedup vs baseline: 2.4983x; 2.4983x over previous
#include <cuda_runtime.h>
#include <cstdint>

#define Bv 32
#define Tv 1500
#define Ev 1024
#define Hv 8
#define DKv 128
#define DVv 128
#define Dv 1024
#define SCALING 0.088388347648318447f  // 1/sqrt(128)
#define TCHUNK 12

// Scratch (no allocations allowed)
__device__ float g_q[Bv * Hv * DKv];           // tanh(dec_z@Wq + bq)
__device__ float g_c[Bv * Hv * DVv];           // u @ Wv
__device__ float g_WkT[Hv * DKv * Ev];         // Wk transposed: [h][n][e]
__device__ float g_up[TCHUNK * Bv * Hv * Ev];  // u partials over t-chunks

// ---------------------------------------------------------------------------
// PTX helpers (arch-agnostic: sm_80-level only; no tcgen05 on this harness)
// ---------------------------------------------------------------------------
__device__ __forceinline__ uint32_t smem_u32(const void* p) {
    uint32_t a;
    asm("{ .reg .u64 t; cvta.to.shared.u64 t, %1; cvt.u32.u64 %0, t; }" : "=r"(a) : "l"(p));
    return a;
}
__device__ __forceinline__ uint32_t to_tf32(float f) {
    uint32_t r;
    asm("cvt.rna.tf32.f32 %0, %1;" : "=r"(r) : "f"(f));
    return r;
}
#define CP16(sm, gm, sz) \
    asm volatile("cp.async.cg.shared.global [%0], [%1], 16, %2;" ::"r"(sm), "l"(gm), "r"(sz) : "memory")
#define CP_COMMIT() asm volatile("cp.async.commit_group;" ::: "memory")
#define CP_WAIT0() asm volatile("cp.async.wait_group 0;" ::: "memory")

__device__ __forceinline__ void mma_tf32(float* d, uint32_t a0, uint32_t a1, uint32_t a2,
                                         uint32_t a3, uint32_t b0, uint32_t b1) {
    asm volatile(
        "mma.sync.aligned.m16n8k8.row.col.f32.tf32.tf32.f32 "
        "{%0,%1,%2,%3}, {%4,%5,%6,%7}, {%8,%9}, {%0,%1,%2,%3};"
        : "+f"(d[0]), "+f"(d[1]), "+f"(d[2]), "+f"(d[3])
        : "r"(a0), "r"(a1), "r"(a2), "r"(a3), "r"(b0), "r"(b1));
}

// ---------------------------------------------------------------------------
// Length read with dtype sniff (int64 declared, int32 in practice)
// ---------------------------------------------------------------------------
__device__ __forceinline__ int get_len(const int* __restrict__ L, int b) {
    bool is64 = (L[1] == 0);
    return is64 ? L[2 * b] : L[b];
}

// ---------------------------------------------------------------------------
// q[b,h,k] = tanh(dec_z[b,:]·Wq[h,:,k] + bq[h,k])
// ---------------------------------------------------------------------------
__global__ __launch_bounds__(128) void q_kernel(const float* __restrict__ dec_z,
                                                const float* __restrict__ Wq,
                                                const float* __restrict__ bq) {
    int h = blockIdx.x, b = blockIdx.y;
    int k = threadIdx.x;
    __shared__ float zs[Dv];
    for (int i = k; i < Dv; i += 128) zs[i] = dec_z[b * Dv + i];
    __syncthreads();
    float acc = bq[h * DKv + k];
    const float* W = Wq + (size_t)h * Dv * DKv + k;
#pragma unroll 8
    for (int d = 0; d < Dv; d++) acc += zs[d] * W[(size_t)d * DKv];
    g_q[(b * Hv + h) * DKv + k] = tanhf(acc);
}

// ---------------------------------------------------------------------------
// WkT[h][n][e] = Wk[h][e][n]  (B tiles then load K-major coalesced)
// ---------------------------------------------------------------------------
__global__ __launch_bounds__(256) void wkT_kernel(const float* __restrict__ Wk) {
    __shared__ float tile[32][33];
    int e0 = blockIdx.x * 32, n0 = blockIdx.y * 32, h = blockIdx.z;
    int tx = threadIdx.x & 31, ty = threadIdx.x >> 5;  // 32x8
    for (int i = ty; i < 32; i += 8)
        tile[i][tx] = Wk[((size_t)h * Ev + e0 + i) * DKv + n0 + tx];
    __syncthreads();
    for (int i = ty; i < 32; i += 8)
        g_WkT[((size_t)h * DKv + n0 + i) * Ev + e0 + tx] = tile[tx][i];
}

// ---------------------------------------------------------------------------
// e[b,h,t] = sum_n tanh( (enc@Wk[h])[t,n] ) * q[b,h,n]
// tf32 mma.sync GEMM: per CTA = (h, 128-row t-tile, b). M=128,N=128,K=1024.
// 8 warps as 4(M)x2(N); warp tile 32x64; m16n8k8 fragments from SMEM
// (stride-36-word rows => conflict-free fragment LDS). cp.async double buffer.
// ---------------------------------------------------------------------------
#define TKc 32
#define NCH (Ev / TKc)   // 32 chunks
#define LDW 36           // smem row stride in words

__global__ __launch_bounds__(256, 2) void e_tc_kernel(const float* __restrict__ enc,
                                                      float* __restrict__ ebuf) {
    __shared__ float sA[2][128 * LDW];
    __shared__ float sB[2][128 * LDW];
    __shared__ float qs[DKv];
    __shared__ float red[2][128];

    int tid = threadIdx.x, wid = tid >> 5, lane = tid & 31;
    int h = blockIdx.x, tile = blockIdx.y, b = blockIdx.z;
    int t0 = tile * 128;
    int wm = wid & 3, wn = wid >> 1 & 0;  // placeholder; real below
    wn = wid >> 2;                        // 0..1
    int lane4 = lane >> 2, laneq = lane & 3;

    if (tid < DKv) qs[tid] = g_q[(b * Hv + h) * DKv + tid];

    const float* A = enc + (size_t)b * Tv * Ev;
    const float* Wt = g_WkT + (size_t)h * DKv * Ev;

    uint32_t sbA[2] = {smem_u32(sA[0]), smem_u32(sA[1])};
    uint32_t sbB[2] = {smem_u32(sB[0]), smem_u32(sB[1])};

    // Issue loads for chunk c into buffer p
    auto issue = [&](int c, int p) {
        int k0 = c * TKc;
#pragma unroll
        for (int r = 0; r < 4; r++) {
            int idx = r * 256 + tid;
            int row = idx >> 3, seg = idx & 7;
            int t = t0 + row;
            uint32_t sz = (t < Tv) ? 16u : 0u;
            CP16(sbA[p] + row * (LDW * 4) + seg * 16,
                 A + (size_t)t * Ev + k0 + seg * 4, sz);
        }
#pragma unroll
        for (int r = 0; r < 4; r++) {
            int idx = r * 256 + tid;
            int row = idx >> 3, seg = idx & 7;
            CP16(sbB[p] + row * (LDW * 4) + seg * 16,
                 Wt + (size_t)row * Ev + k0 + seg * 4, 16u);
        }
        CP_COMMIT();
    };

    float d[2][8][4];
#pragma unroll
    for (int ms = 0; ms < 2; ms++)
#pragma unroll
        for (int ns = 0; ns < 8; ns++)
#pragma unroll
            for (int j = 0; j < 4; j++) d[ms][ns][j] = 0.f;

    issue(0, 0);

    for (int c = 0; c < NCH; c++) {
        int p = c & 1;
        CP_WAIT0();
        __syncthreads();
        if (c + 1 < NCH) issue(c + 1, p ^ 1);  // other buffer: safe, compute of it ended pre-sync
        const float* cA = sA[p];
        const float* cB = sB[p];
#pragma unroll
        for (int kk = 0; kk < 4; kk++) {
            int kb = kk * 8 + laneq;
            uint32_t bf[8][2];
#pragma unroll
            for (int ns = 0; ns < 8; ns++) {
                int n = wn * 64 + ns * 8 + lane4;
                bf[ns][0] = to_tf32(cB[n * LDW + kb]);
                bf[ns][1] = to_tf32(cB[n * LDW + kb + 4]);
            }
#pragma unroll
            for (int ms = 0; ms < 2; ms++) {
                int r0 = wm * 32 + ms * 16 + lane4;
                uint32_t a0 = to_tf32(cA[r0 * LDW + kb]);
                uint32_t a1 = to_tf32(cA[(r0 + 8) * LDW + kb]);
                uint32_t a2 = to_tf32(cA[r0 * LDW + kb + 4]);
                uint32_t a3 = to_tf32(cA[(r0 + 8) * LDW + kb + 4]);
#pragma unroll
                for (int ns = 0; ns < 8; ns++)
                    mma_tf32(d[ms][ns], a0, a1, a2, a3, bf[ns][0], bf[ns][1]);
            }
        }
        __syncthreads();  // all warps done with buf p before it is refilled next iter
    }

    // Epilogue: tanh + q-dot, reduce 4 lanes (cols) via shfl, cross-warp via smem
#pragma unroll
    for (int ms = 0; ms < 2; ms++) {
        float pr0 = 0.f, pr1 = 0.f;
#pragma unroll
        for (int ns = 0; ns < 8; ns++) {
            int n0 = wn * 64 + ns * 8 + 2 * laneq;
            float q0 = qs[n0], q1 = qs[n0 + 1];
            pr0 += tanhf(d[ms][ns][0]) * q0 + tanhf(d[ms][ns][1]) * q1;
            pr1 += tanhf(d[ms][ns][2]) * q0 + tanhf(d[ms][ns][3]) * q1;
        }
#pragma unroll
        for (int o = 1; o < 4; o <<= 1) {
            pr0 += __shfl_xor_sync(0xffffffffu, pr0, o);
            pr1 += __shfl_xor_sync(0xffffffffu, pr1, o);
        }
        if (laneq == 0) {
            int r = wm * 32 + ms * 16 + lane4;
            red[wn][r] = pr0;
            red[wn][r + 8] = pr1;
        }
    }
    __syncthreads();
    if (tid < 128) {
        int t = t0 + tid;
        if (t < Tv)
            ebuf[(size_t)(b * Hv + h) * Tv + t] = red[0][tid] + red[1][tid];
    }
}

// ---------------------------------------------------------------------------
// Masked softmax over T, in place. w = softmax(SCALING*e) on t<len, 0 else.
// ---------------------------------------------------------------------------
__global__ __launch_bounds__(256) void softmax_kernel(float* __restrict__ wbuf,
                                                      const int* __restrict__ lens) {
    int bh = blockIdx.x;
    int b = bh / Hv;
    int len = get_len(lens, b);
    int tid = threadIdx.x;
    __shared__ float s[Tv];
    __shared__ float red[16];
    float* row = wbuf + (size_t)bh * Tv;
    for (int t = tid; t < Tv; t += 256) s[t] = row[t];
    __syncthreads();

    float m = -1e30f;
    for (int t = tid; t < len; t += 256) m = fmaxf(m, s[t]);
#pragma unroll
    for (int o = 16; o; o >>= 1) m = fmaxf(m, __shfl_xor_sync(0xffffffffu, m, o));
    if ((tid & 31) == 0) red[tid >> 5] = m;
    __syncthreads();
    m = red[0];
#pragma unroll
    for (int i = 1; i < 8; i++) m = fmaxf(m, red[i]);
    float M = SCALING * m;

    float lsum = 0.f;
    for (int t = tid; t < len; t += 256) lsum += expf(SCALING * s[t] - M);
#pragma unroll
    for (int o = 16; o; o >>= 1) lsum += __shfl_xor_sync(0xffffffffu, lsum, o);
    if ((tid & 31) == 0) red[8 + (tid >> 5)] = lsum;
    __syncthreads();
    float total = 0.f;
#pragma unroll
    for (int i = 0; i < 8; i++) total += red[8 + i];
    float inv = 1.f / total;

    for (int t = tid; t < Tv; t += 256)
        row[t] = (t < len) ? expf(SCALING * s[t] - M) * inv : 0.f;
}

// ---------------------------------------------------------------------------
// u partials: g_up[tc][b][h][d] = sum_{t in chunk tc} w[b,h,t] * enc[b,t,d]
// ---------------------------------------------------------------------------
__global__ __launch_bounds__(256) void u_kernel(const float* __restrict__ enc,
                                                const float* __restrict__ wbuf) {
    int chunk = blockIdx.x, tc = blockIdx.y, b = blockIdx.z;
    int d = chunk * 256 + threadIdx.x;
    int t0 = tc * 128;
    int tmax = min(128, Tv - t0);
    __shared__ float ws[Hv][128];
    float acc[Hv] = {0.f, 0.f, 0.f, 0.f, 0.f, 0.f, 0.f, 0.f};
#pragma unroll
    for (int r = 0; r < 4; r++) {
        int f = r * 256 + threadIdx.x;
        int h = f >> 7, tt = f & 127;
        int t = t0 + tt;
        ws[h][tt] = (t < Tv) ? wbuf[((size_t)(b * Hv + h)) * Tv + t] : 0.f;
    }
    __syncthreads();
    const float* A = enc + (size_t)b * Tv * Ev;
    for (int tt = 0; tt < tmax; tt++) {
        float x = A[(size_t)(t0 + tt) * Ev + d];
#pragma unroll
        for (int h = 0; h < Hv; h++) acc[h] += ws[h][tt] * x;
    }
#pragma unroll
    for (int h = 0; h < Hv; h++)
        g_up[(((size_t)tc * Bv + b) * Hv + h) * Ev + d] = acc[h];
}

// ---------------------------------------------------------------------------
// c[b,h,v] = u[b,h,:]·Wv[h,:,v]  (u = sum of partials, reduced inline)
// ---------------------------------------------------------------------------
__global__ __launch_bounds__(128) void c_kernel(const float* __restrict__ Wv) {
    int h = blockIdx.x, b = blockIdx.y;
    int v = threadIdx.x;
    __shared__ float us[Ev];
    for (int i = v; i < Ev; i += 128) {
        float s = 0.f;
#pragma unroll
        for (int tc = 0; tc < TCHUNK; tc++)
            s += g_up[(((size_t)tc * Bv + b) * Hv + h) * Ev + i];
        us[i] = s;
    }
    __syncthreads();
    float acc = 0.f;
    const float* W = Wv + (size_t)h * Ev * DVv + v;
#pragma unroll 8
    for (int d = 0; d < Ev; d++) acc += us[d] * W[(size_t)d * DVv];
    g_c[(b * Hv + h) * DVv + v] = acc;
}

// ---------------------------------------------------------------------------
// out[b,e] = c_flat[b,:]·Wo[:,e]
// ---------------------------------------------------------------------------
__global__ __launch_bounds__(256) void out_kernel(const float* __restrict__ Wo,
                                                  float* __restrict__ out) {
    int chunk = blockIdx.x, b = blockIdx.y;
    int e = chunk * 256 + threadIdx.x;
    __shared__ float cs[Hv * DVv];
    for (int i = threadIdx.x; i < Hv * DVv; i += 256) cs[i] = g_c[b * Hv * DVv + i];
    __syncthreads();
    float acc = 0.f;
#pragma unroll 8
    for (int i = 0; i < Hv * DVv; i++) acc += cs[i] * Wo[(size_t)i * Ev + e];
    out[(size_t)b * Ev + e] = acc;
}

// ---------------------------------------------------------------------------
extern "C" void kernel_launch(void* const* d_in, const int* in_sizes, int n_in,
                              void* d_out, int out_size) {
    const float* enc   = (const float*)d_in[0];
    const int*   lens  = (const int*)d_in[1];
    const float* dec_z = (const float*)d_in[2];
    const float* Wq    = (const float*)d_in[3];
    const float* bq    = (const float*)d_in[4];
    const float* Wk    = (const float*)d_in[5];
    const float* Wv    = (const float*)d_in[6];
    const float* Wo    = (const float*)d_in[7];

    float* out  = (float*)d_out;   // (B,E)
    float* wbuf = out + Bv * Ev;   // (B,H,T): e logits, then w in place

    q_kernel<<<dim3(Hv, Bv), 128>>>(dec_z, Wq, bq);
    wkT_kernel<<<dim3(Ev / 32, DKv / 32, Hv), 256>>>(Wk);
    e_tc_kernel<<<dim3(Hv, (Tv + 127) / 128, Bv), 256>>>(enc, wbuf);
    softmax_kernel<<<Bv * Hv, 256>>>(wbuf, lens);
    u_kernel<<<dim3(Ev / 256, TCHUNK, Bv), 256>>>(enc, wbuf);
    c_kernel<<<dim3(Hv, Bv), 128>>>(Wv);
    out_kernel<<<dim3(Ev / 256, Bv), 256>>>(Wo, out);
}

// round 5
// speedup vs baseline: 4.2857x; 1.7154x over previous
#include <cuda_runtime.h>
#include <cuda_fp16.h>
#include <cstdint>

#define Bv 32
#define Tv 1500
#define Ev 1024
#define Hv 8
#define DKv 128
#define DVv 128
#define Dv 1024
#define SCALING 0.088388347648318447f  // 1/sqrt(128)
#define TCHUNK 12

// Scratch (no allocations allowed)
__device__ float g_q[Bv * Hv * DKv];            // tanh(dec_z@Wq + bq)
__device__ float g_c[Bv * Hv * DVv];            // u @ Wv
__device__ float g_up[TCHUNK * Bv * Hv * Ev];   // u partials over t-chunks
__device__ __half g_enc16[(size_t)Bv * Tv * Ev];   // enc in fp16 (98.3 MB)
__device__ __half g_wkT16[(size_t)Hv * DKv * Ev];  // Wk^T in fp16: [h][n][e]

// ---------------------------------------------------------------------------
// PTX helpers (sm_80-level only; tcgen05 is not accepted by this harness)
// ---------------------------------------------------------------------------
__device__ __forceinline__ uint32_t smem_u32(const void* p) {
    uint32_t a;
    asm("{ .reg .u64 t; cvta.to.shared.u64 t, %1; cvt.u32.u64 %0, t; }" : "=r"(a) : "l"(p));
    return a;
}
#define CP16(sm, gm, sz) \
    asm volatile("cp.async.cg.shared.global [%0], [%1], 16, %2;" ::"r"(sm), "l"(gm), "r"(sz) : "memory")
#define CP_COMMIT() asm volatile("cp.async.commit_group;" ::: "memory")
#define CP_WAIT0() asm volatile("cp.async.wait_group 0;" ::: "memory")
#define LDSM4(r0, r1, r2, r3, a)                                             \
    asm volatile("ldmatrix.sync.aligned.m8n8.x4.shared.b16 {%0,%1,%2,%3}, [%4];" \
                 : "=r"(r0), "=r"(r1), "=r"(r2), "=r"(r3) : "r"(a))

__device__ __forceinline__ void mma_f16(float* d, uint32_t a0, uint32_t a1, uint32_t a2,
                                        uint32_t a3, uint32_t b0, uint32_t b1) {
    asm volatile(
        "mma.sync.aligned.m16n8k16.row.col.f32.f16.f16.f32 "
        "{%0,%1,%2,%3}, {%4,%5,%6,%7}, {%8,%9}, {%0,%1,%2,%3};"
        : "+f"(d[0]), "+f"(d[1]), "+f"(d[2]), "+f"(d[3])
        : "r"(a0), "r"(a1), "r"(a2), "r"(a3), "r"(b0), "r"(b1));
}
__device__ __forceinline__ uint32_t sw128(uint32_t o) { return o ^ ((o >> 3) & 0x70); }

// ---------------------------------------------------------------------------
// Length read with dtype sniff (int64 declared, int32 in practice)
// ---------------------------------------------------------------------------
__device__ __forceinline__ int get_len(const int* __restrict__ L, int b) {
    bool is64 = (L[1] == 0);
    return is64 ? L[2 * b] : L[b];
}

// ---------------------------------------------------------------------------
// enc -> fp16 (round-to-nearest). 8 floats per thread.
// ---------------------------------------------------------------------------
__global__ __launch_bounds__(256) void enc16_kernel(const float* __restrict__ enc) {
    size_t base = ((size_t)blockIdx.x * 256 + threadIdx.x) * 8;
    float4 v0 = *(const float4*)(enc + base);
    float4 v1 = *(const float4*)(enc + base + 4);
    __half2 h[4];
    h[0] = __floats2half2_rn(v0.x, v0.y);
    h[1] = __floats2half2_rn(v0.z, v0.w);
    h[2] = __floats2half2_rn(v1.x, v1.y);
    h[3] = __floats2half2_rn(v1.z, v1.w);
    *(uint4*)(g_enc16 + base) = *(uint4*)h;
}

// ---------------------------------------------------------------------------
// wkT16[h][n][e] = fp16(Wk[h][e][n])
// ---------------------------------------------------------------------------
__global__ __launch_bounds__(256) void wkT16_kernel(const float* __restrict__ Wk) {
    __shared__ float tile[32][33];
    int e0 = blockIdx.x * 32, n0 = blockIdx.y * 32, h = blockIdx.z;
    int tx = threadIdx.x & 31, ty = threadIdx.x >> 5;
    for (int i = ty; i < 32; i += 8)
        tile[i][tx] = Wk[((size_t)h * Ev + e0 + i) * DKv + n0 + tx];
    __syncthreads();
    for (int i = ty; i < 32; i += 8)
        g_wkT16[((size_t)h * DKv + n0 + i) * Ev + e0 + tx] = __float2half_rn(tile[tx][i]);
}

// ---------------------------------------------------------------------------
// q[b,h,k] = tanh(dec_z[b,:]·Wq[h,:,k] + bq[h,k])
// ---------------------------------------------------------------------------
__global__ __launch_bounds__(128) void q_kernel(const float* __restrict__ dec_z,
                                                const float* __restrict__ Wq,
                                                const float* __restrict__ bq) {
    int h = blockIdx.x, b = blockIdx.y;
    int k = threadIdx.x;
    __shared__ float zs[Dv];
    for (int i = k; i < Dv; i += 128) zs[i] = dec_z[b * Dv + i];
    __syncthreads();
    float acc = bq[h * DKv + k];
    const float* W = Wq + (size_t)h * Dv * DKv + k;
#pragma unroll 8
    for (int d = 0; d < Dv; d++) acc += zs[d] * W[(size_t)d * DKv];
    g_q[(b * Hv + h) * DKv + k] = tanhf(acc);
}

// ---------------------------------------------------------------------------
// e[b,h,t] = sum_n tanh( (enc@Wk[h])[t,n] ) * q[b,h,n]
// fp16 m16n8k16 mma GEMM: per CTA = (h, 128-t tile, b). M=128,N=128,K=1024.
// 8 warps as 4(M)x2(N), warp tile 32x64. SMEM fp16 tiles (128B rows, SW128),
// cp.async double buffer, ldmatrix.x4 fragment loads. tanh+q-dot epilogue.
// ---------------------------------------------------------------------------
#define ECH 64                 // K halves per stage (128 bytes per row)
#define ENCH (Ev / ECH)        // 16 chunks
#define EST 16384              // one tile stage: 128 rows * 128 B
#define OFF_QS (4 * EST)       // 65536
#define OFF_RED (OFF_QS + 512)
#define E_SMEM (OFF_RED + 1024)

__global__ __launch_bounds__(256, 2) void e_tc_kernel(float* __restrict__ ebuf) {
    extern __shared__ __align__(16) char dsm[];
    float* qs = (float*)(dsm + OFF_QS);
    float* red = (float*)(dsm + OFF_RED);  // [2][128]

    int tid = threadIdx.x, wid = tid >> 5, lane = tid & 31;
    int h = blockIdx.x, tile = blockIdx.y, b = blockIdx.z;
    int t0 = tile * 128;
    int wm = wid & 3, wn = wid >> 2;
    int lane4 = lane >> 2, laneq = lane & 3;

    if (tid < DKv) qs[tid] = g_q[(b * Hv + h) * DKv + tid];

    const __half* A = g_enc16 + (size_t)b * Tv * Ev;
    const __half* Wt = g_wkT16 + (size_t)h * DKv * Ev;

    uint32_t base = smem_u32(dsm);
    uint32_t sbA[2] = {base, base + EST};
    uint32_t sbB[2] = {base + 2 * EST, base + 3 * EST};

    auto issue = [&](int c, int p) {
        int k0 = c * ECH;
#pragma unroll
        for (int r = 0; r < 4; r++) {
            int idx = r * 256 + tid;
            int row = idx >> 3, seg = idx & 7;
            int t = t0 + row;
            uint32_t sz = (t < Tv) ? 16u : 0u;
            CP16(sbA[p] + sw128(row * 128 + seg * 16),
                 A + (size_t)t * Ev + k0 + seg * 8, sz);
        }
#pragma unroll
        for (int r = 0; r < 4; r++) {
            int idx = r * 256 + tid;
            int row = idx >> 3, seg = idx & 7;
            CP16(sbB[p] + sw128(row * 128 + seg * 16),
                 Wt + (size_t)row * Ev + k0 + seg * 8, 16u);
        }
        CP_COMMIT();
    };

    float d[2][8][4];
#pragma unroll
    for (int ms = 0; ms < 2; ms++)
#pragma unroll
        for (int ns = 0; ns < 8; ns++)
#pragma unroll
            for (int j = 0; j < 4; j++) d[ms][ns][j] = 0.f;

    issue(0, 0);

    // Per-lane ldmatrix row/col (bytes) precomputed; kk advances column.
    // A x4 tiles -> regs a0..a3: (rows R..R+7,k0-7)(R+8..15,k0-7)(R..R+7,k8-15)(R+8..15,k8-15)
    int rowAl = (lane & 7) + ((lane >> 3) & 1) * 8;
    int colAl = ((lane >> 4) & 1) * 16;
    // B x4 tiles -> regs: (n..n+7,k0-7)(n..n+7,k8-15)(n+8..15,k0-7)(n+8..15,k8-15)
    int rowBl = (lane & 7) + ((lane >> 4) & 1) * 8;
    int colBl = ((lane >> 3) & 1) * 16;

    for (int c = 0; c < ENCH; c++) {
        int p = c & 1;
        CP_WAIT0();
        __syncthreads();
        if (c + 1 < ENCH) issue(c + 1, p ^ 1);
#pragma unroll
        for (int kk = 0; kk < 4; kk++) {
            int kb = kk * 32;  // byte offset of this K16 slice
            uint32_t af[2][4];
#pragma unroll
            for (int ms = 0; ms < 2; ms++) {
                int row = wm * 32 + ms * 16 + rowAl;
                LDSM4(af[ms][0], af[ms][1], af[ms][2], af[ms][3],
                      sbA[p] + sw128(row * 128 + colAl + kb));
            }
            uint32_t bf[8][2];
#pragma unroll
            for (int pp = 0; pp < 4; pp++) {
                int row = wn * 64 + pp * 16 + rowBl;
                LDSM4(bf[2 * pp][0], bf[2 * pp][1], bf[2 * pp + 1][0], bf[2 * pp + 1][1],
                      sbB[p] + sw128(row * 128 + colBl + kb));
            }
#pragma unroll
            for (int ms = 0; ms < 2; ms++)
#pragma unroll
                for (int ns = 0; ns < 8; ns++)
                    mma_f16(d[ms][ns], af[ms][0], af[ms][1], af[ms][2], af[ms][3],
                            bf[ns][0], bf[ns][1]);
        }
        __syncthreads();
    }

    // Epilogue: tanh + q-dot; reduce over cols (4 lanes) via shfl, warps via smem
#pragma unroll
    for (int ms = 0; ms < 2; ms++) {
        float pr0 = 0.f, pr1 = 0.f;
#pragma unroll
        for (int ns = 0; ns < 8; ns++) {
            int n0 = wn * 64 + ns * 8 + 2 * laneq;
            float q0 = qs[n0], q1 = qs[n0 + 1];
            pr0 += tanhf(d[ms][ns][0]) * q0 + tanhf(d[ms][ns][1]) * q1;
            pr1 += tanhf(d[ms][ns][2]) * q0 + tanhf(d[ms][ns][3]) * q1;
        }
#pragma unroll
        for (int o = 1; o < 4; o <<= 1) {
            pr0 += __shfl_xor_sync(0xffffffffu, pr0, o);
            pr1 += __shfl_xor_sync(0xffffffffu, pr1, o);
        }
        if (laneq == 0) {
            int r = wm * 32 + ms * 16 + lane4;
            red[wn * 128 + r] = pr0;
            red[wn * 128 + r + 8] = pr1;
        }
    }
    __syncthreads();
    if (tid < 128) {
        int t = t0 + tid;
        if (t < Tv)
            ebuf[(size_t)(b * Hv + h) * Tv + t] = red[tid] + red[128 + tid];
    }
}

// ---------------------------------------------------------------------------
// Masked softmax over T, in place. w = softmax(SCALING*e) on t<len, 0 else.
// ---------------------------------------------------------------------------
__global__ __launch_bounds__(256) void softmax_kernel(float* __restrict__ wbuf,
                                                      const int* __restrict__ lens) {
    int bh = blockIdx.x;
    int b = bh / Hv;
    int len = get_len(lens, b);
    int tid = threadIdx.x;
    __shared__ float s[Tv];
    __shared__ float red[16];
    float* row = wbuf + (size_t)bh * Tv;
    for (int t = tid; t < Tv; t += 256) s[t] = row[t];
    __syncthreads();

    float m = -1e30f;
    for (int t = tid; t < len; t += 256) m = fmaxf(m, s[t]);
#pragma unroll
    for (int o = 16; o; o >>= 1) m = fmaxf(m, __shfl_xor_sync(0xffffffffu, m, o));
    if ((tid & 31) == 0) red[tid >> 5] = m;
    __syncthreads();
    m = red[0];
#pragma unroll
    for (int i = 1; i < 8; i++) m = fmaxf(m, red[i]);
    float M = SCALING * m;

    float lsum = 0.f;
    for (int t = tid; t < len; t += 256) lsum += expf(SCALING * s[t] - M);
#pragma unroll
    for (int o = 16; o; o >>= 1) lsum += __shfl_xor_sync(0xffffffffu, lsum, o);
    if ((tid & 31) == 0) red[8 + (tid >> 5)] = lsum;
    __syncthreads();
    float total = 0.f;
#pragma unroll
    for (int i = 0; i < 8; i++) total += red[8 + i];
    float inv = 1.f / total;

    for (int t = tid; t < Tv; t += 256)
        row[t] = (t < len) ? expf(SCALING * s[t] - M) * inv : 0.f;
}

// ---------------------------------------------------------------------------
// u partials: g_up[tc][b][h][d] = sum_{t in chunk} w[b,h,t] * enc[b,t,d]
// Chunks entirely beyond len contribute zero -> skip enc reads.
// ---------------------------------------------------------------------------
__global__ __launch_bounds__(256) void u_kernel(const float* __restrict__ enc,
                                                const float* __restrict__ wbuf,
                                                const int* __restrict__ lens) {
    int chunk = blockIdx.x, tc = blockIdx.y, b = blockIdx.z;
    int d = chunk * 256 + threadIdx.x;
    int len = get_len(lens, b);
    int t0 = tc * 128;
    if (t0 >= len) {
#pragma unroll
        for (int h = 0; h < Hv; h++)
            g_up[(((size_t)tc * Bv + b) * Hv + h) * Ev + d] = 0.f;
        return;
    }
    int tmax = min(min(128, Tv - t0), len - t0);
    __shared__ float ws[Hv][128];
    float acc[Hv] = {0.f, 0.f, 0.f, 0.f, 0.f, 0.f, 0.f, 0.f};
#pragma unroll
    for (int r = 0; r < 4; r++) {
        int f = r * 256 + threadIdx.x;
        int h = f >> 7, tt = f & 127;
        int t = t0 + tt;
        ws[h][tt] = (t < Tv) ? wbuf[((size_t)(b * Hv + h)) * Tv + t] : 0.f;
    }
    __syncthreads();
    const float* A = enc + (size_t)b * Tv * Ev;
    for (int tt = 0; tt < tmax; tt++) {
        float x = A[(size_t)(t0 + tt) * Ev + d];
#pragma unroll
        for (int h = 0; h < Hv; h++) acc[h] += ws[h][tt] * x;
    }
#pragma unroll
    for (int h = 0; h < Hv; h++)
        g_up[(((size_t)tc * Bv + b) * Hv + h) * Ev + d] = acc[h];
}

// ---------------------------------------------------------------------------
// c[b,h,v] = u[b,h,:]·Wv[h,:,v]  (partials reduced inline)
// ---------------------------------------------------------------------------
__global__ __launch_bounds__(128) void c_kernel(const float* __restrict__ Wv) {
    int h = blockIdx.x, b = blockIdx.y;
    int v = threadIdx.x;
    __shared__ float us[Ev];
    for (int i = v; i < Ev; i += 128) {
        float s = 0.f;
#pragma unroll
        for (int tc = 0; tc < TCHUNK; tc++)
            s += g_up[(((size_t)tc * Bv + b) * Hv + h) * Ev + i];
        us[i] = s;
    }
    __syncthreads();
    float acc = 0.f;
    const float* W = Wv + (size_t)h * Ev * DVv + v;
#pragma unroll 8
    for (int d = 0; d < Ev; d++) acc += us[d] * W[(size_t)d * DVv];
    g_c[(b * Hv + h) * DVv + v] = acc;
}

// ---------------------------------------------------------------------------
// out[b,e] = c_flat[b,:]·Wo[:,e]
// ---------------------------------------------------------------------------
__global__ __launch_bounds__(256) void out_kernel(const float* __restrict__ Wo,
                                                  float* __restrict__ out) {
    int chunk = blockIdx.x, b = blockIdx.y;
    int e = chunk * 256 + threadIdx.x;
    __shared__ float cs[Hv * DVv];
    for (int i = threadIdx.x; i < Hv * DVv; i += 256) cs[i] = g_c[b * Hv * DVv + i];
    __syncthreads();
    float acc = 0.f;
#pragma unroll 8
    for (int i = 0; i < Hv * DVv; i++) acc += cs[i] * Wo[(size_t)i * Ev + e];
    out[(size_t)b * Ev + e] = acc;
}

// ---------------------------------------------------------------------------
extern "C" void kernel_launch(void* const* d_in, const int* in_sizes, int n_in,
                              void* d_out, int out_size) {
    const float* enc   = (const float*)d_in[0];
    const int*   lens  = (const int*)d_in[1];
    const float* dec_z = (const float*)d_in[2];
    const float* Wq    = (const float*)d_in[3];
    const float* bq    = (const float*)d_in[4];
    const float* Wk    = (const float*)d_in[5];
    const float* Wv    = (const float*)d_in[6];
    const float* Wo    = (const float*)d_in[7];

    float* out  = (float*)d_out;   // (B,E)
    float* wbuf = out + Bv * Ev;   // (B,H,T): e logits, then w in place

    static int smem_set = 0;
    if (!smem_set) {
        cudaFuncSetAttribute(e_tc_kernel, cudaFuncAttributeMaxDynamicSharedMemorySize, E_SMEM);
        smem_set = 1;
    }

    enc16_kernel<<<(Bv * Tv * Ev) / (256 * 8), 256>>>(enc);
    wkT16_kernel<<<dim3(Ev / 32, DKv / 32, Hv), 256>>>(Wk);
    q_kernel<<<dim3(Hv, Bv), 128>>>(dec_z, Wq, bq);
    e_tc_kernel<<<dim3(Hv, (Tv + 127) / 128, Bv), 256, E_SMEM>>>(wbuf);
    softmax_kernel<<<Bv * Hv, 256>>>(wbuf, lens);
    u_kernel<<<dim3(Ev / 256, TCHUNK, Bv), 256>>>(enc, wbuf, lens);
    c_kernel<<<dim3(Hv, Bv), 128>>>(Wv);
    out_kernel<<<dim3(Ev / 256, Bv), 256>>>(Wo, out);
}

// round 6
// speedup vs baseline: 4.4787x; 1.0450x over previous
#include <cuda_runtime.h>
#include <cuda_fp16.h>
#include <cstdint>

#define Bv 32
#define Tv 1500
#define Ev 1024
#define Hv 8
#define DKv 128
#define DVv 128
#define Dv 1024
#define SCALING 0.088388347648318447f  // 1/sqrt(128)
#define TCHUNK 12

// Scratch (no allocations allowed)
__device__ float g_q[Bv * Hv * DKv];            // tanh(dec_z@Wq + bq)
__device__ float g_c[Bv * Hv * DVv];            // u @ Wv
__device__ float g_up[TCHUNK * Bv * Hv * Ev];   // u partials over t-chunks
__device__ __half g_enc16[(size_t)Bv * Tv * Ev];   // enc in fp16 (98.3 MB)
__device__ __half g_wkT16[(size_t)Hv * DKv * Ev];  // Wk^T in fp16: [h][n][e]

// ---------------------------------------------------------------------------
// PTX helpers (sm_80-level only; tcgen05 is rejected by this harness target)
// ---------------------------------------------------------------------------
__device__ __forceinline__ uint32_t smem_u32(const void* p) {
    uint32_t a;
    asm("{ .reg .u64 t; cvta.to.shared.u64 t, %1; cvt.u32.u64 %0, t; }" : "=r"(a) : "l"(p));
    return a;
}
#define CP16(sm, gm, sz) \
    asm volatile("cp.async.cg.shared.global [%0], [%1], 16, %2;" ::"r"(sm), "l"(gm), "r"(sz) : "memory")
#define CP_COMMIT() asm volatile("cp.async.commit_group;" ::: "memory")
#define CP_WAIT1() asm volatile("cp.async.wait_group 1;" ::: "memory")
#define LDSM4(r0, r1, r2, r3, a)                                             \
    asm volatile("ldmatrix.sync.aligned.m8n8.x4.shared.b16 {%0,%1,%2,%3}, [%4];" \
                 : "=r"(r0), "=r"(r1), "=r"(r2), "=r"(r3) : "r"(a))

__device__ __forceinline__ void mma_f16(float* d, uint32_t a0, uint32_t a1, uint32_t a2,
                                        uint32_t a3, uint32_t b0, uint32_t b1) {
    asm volatile(
        "mma.sync.aligned.m16n8k16.row.col.f32.f16.f16.f32 "
        "{%0,%1,%2,%3}, {%4,%5,%6,%7}, {%8,%9}, {%0,%1,%2,%3};"
        : "+f"(d[0]), "+f"(d[1]), "+f"(d[2]), "+f"(d[3])
        : "r"(a0), "r"(a1), "r"(a2), "r"(a3), "r"(b0), "r"(b1));
}
__device__ __forceinline__ uint32_t sw128(uint32_t o) { return o ^ ((o >> 3) & 0x70); }

// ---------------------------------------------------------------------------
// Length read with dtype sniff (int64 declared, int32 in practice)
// ---------------------------------------------------------------------------
__device__ __forceinline__ int get_len(const int* __restrict__ L, int b) {
    bool is64 = (L[1] == 0);
    return is64 ? L[2 * b] : L[b];
}

// ---------------------------------------------------------------------------
// enc -> fp16 (round-to-nearest). 8 floats per thread.
// ---------------------------------------------------------------------------
__global__ __launch_bounds__(256) void enc16_kernel(const float* __restrict__ enc) {
    size_t base = ((size_t)blockIdx.x * 256 + threadIdx.x) * 8;
    float4 v0 = *(const float4*)(enc + base);
    float4 v1 = *(const float4*)(enc + base + 4);
    __half2 h[4];
    h[0] = __floats2half2_rn(v0.x, v0.y);
    h[1] = __floats2half2_rn(v0.z, v0.w);
    h[2] = __floats2half2_rn(v1.x, v1.y);
    h[3] = __floats2half2_rn(v1.z, v1.w);
    *(uint4*)(g_enc16 + base) = *(uint4*)h;
}

// ---------------------------------------------------------------------------
// wkT16[h][n][e] = fp16(Wk[h][e][n])
// ---------------------------------------------------------------------------
__global__ __launch_bounds__(256) void wkT16_kernel(const float* __restrict__ Wk) {
    __shared__ float tile[32][33];
    int e0 = blockIdx.x * 32, n0 = blockIdx.y * 32, h = blockIdx.z;
    int tx = threadIdx.x & 31, ty = threadIdx.x >> 5;
    for (int i = ty; i < 32; i += 8)
        tile[i][tx] = Wk[((size_t)h * Ev + e0 + i) * DKv + n0 + tx];
    __syncthreads();
    for (int i = ty; i < 32; i += 8)
        g_wkT16[((size_t)h * DKv + n0 + i) * Ev + e0 + tx] = __float2half_rn(tile[tx][i]);
}

// ---------------------------------------------------------------------------
// q[b,h,k] = tanh(dec_z[b,:]·Wq[h,:,k] + bq[h,k])
// ---------------------------------------------------------------------------
__global__ __launch_bounds__(128) void q_kernel(const float* __restrict__ dec_z,
                                                const float* __restrict__ Wq,
                                                const float* __restrict__ bq) {
    int h = blockIdx.x, b = blockIdx.y;
    int k = threadIdx.x;
    __shared__ float zs[Dv];
    for (int i = k; i < Dv; i += 128) zs[i] = dec_z[b * Dv + i];
    __syncthreads();
    float acc = bq[h * DKv + k];
    const float* W = Wq + (size_t)h * Dv * DKv + k;
#pragma unroll 8
    for (int d = 0; d < Dv; d++) acc += zs[d] * W[(size_t)d * DKv];
    g_q[(b * Hv + h) * DKv + k] = tanhf(acc);
}

// ---------------------------------------------------------------------------
// e[b,h,t] = sum_n tanh( (enc@Wk[h])[t,n] ) * q[b,h,n]
// fp16 m16n8k16 GEMM: per CTA = (h, 128-t tile, b). M=128,N=128,K=1024.
// 3-stage cp.async ring (wait_group 1, one sync per chunk), precomputed
// swizzled addresses, ldmatrix.x4 fragments, tanh+q-dot epilogue.
// ---------------------------------------------------------------------------
#define ECH 64                 // K halves per stage (128 B per row)
#define ENCH (Ev / ECH)        // 16 chunks
#define EST 16384              // one tile stage: 128 rows * 128 B
#define NSTG 3
#define OFF_QS (2 * NSTG * EST)          // 98304
#define OFF_RED (OFF_QS + 512)
#define E_SMEM (OFF_RED + 1024)          // 99840 (x2 CTAs fits 228KB)

__global__ __launch_bounds__(256, 2) void e_tc_kernel(float* __restrict__ ebuf) {
    extern __shared__ __align__(16) char dsm[];
    float* qs = (float*)(dsm + OFF_QS);
    float* red = (float*)(dsm + OFF_RED);  // [2][128]

    int tid = threadIdx.x, wid = tid >> 5, lane = tid & 31;
    int h = blockIdx.x, tile = blockIdx.y, b = blockIdx.z;
    int t0 = tile * 128;
    int wm = wid & 3, wn = wid >> 2;
    int lane4 = lane >> 2, laneq = lane & 3;

    if (tid < DKv) qs[tid] = g_q[(b * Hv + h) * DKv + tid];

    const __half* A = g_enc16 + (size_t)b * Tv * Ev;
    const __half* Wt = g_wkT16 + (size_t)h * DKv * Ev;

    uint32_t base = smem_u32(dsm);
    // stage s: A at base + s*EST, B at base + (NSTG+s)*EST

    // ---- precomputed store-side addresses (4 rounds per tile) ----
    uint32_t swz[4];
    const __half* pA[4];
    const __half* pB[4];
    uint32_t szA[4];
#pragma unroll
    for (int r = 0; r < 4; r++) {
        int idx = r * 256 + tid;
        int row = idx >> 3, seg = idx & 7;
        swz[r] = sw128(row * 128 + seg * 16);
        int t = t0 + row;
        szA[r] = (t < Tv) ? 16u : 0u;
        pA[r] = A + (size_t)t * Ev + seg * 8;
        pB[r] = Wt + (size_t)row * Ev + seg * 8;
    }

    auto issue = [&](int c, int s) {
        int k0 = c * ECH;
        uint32_t bA = base + s * EST, bB = base + (NSTG + s) * EST;
#pragma unroll
        for (int r = 0; r < 4; r++) CP16(bA + swz[r], pA[r] + k0, szA[r]);
#pragma unroll
        for (int r = 0; r < 4; r++) CP16(bB + swz[r], pB[r] + k0, 16u);
        CP_COMMIT();
    };

    // ---- precomputed ldmatrix-side row terms + swizzle masks ----
    int rowAl = (lane & 7) + ((lane >> 3) & 1) * 8;
    int colAl = ((lane >> 4) & 1) * 16;
    int rowBl = (lane & 7) + ((lane >> 4) & 1) * 8;
    int colBl = ((lane >> 3) & 1) * 16;
    uint32_t aRow[2], aMask[2];
#pragma unroll
    for (int ms = 0; ms < 2; ms++) {
        int row = wm * 32 + ms * 16 + rowAl;
        aRow[ms] = row * 128;
        aMask[ms] = (row & 7) << 4;
    }
    uint32_t bRow[4], bMask[4];
#pragma unroll
    for (int pp = 0; pp < 4; pp++) {
        int row = wn * 64 + pp * 16 + rowBl;
        bRow[pp] = row * 128;
        bMask[pp] = (row & 7) << 4;
    }

    float d[2][8][4];
#pragma unroll
    for (int ms = 0; ms < 2; ms++)
#pragma unroll
        for (int ns = 0; ns < 8; ns++)
#pragma unroll
            for (int j = 0; j < 4; j++) d[ms][ns][j] = 0.f;

    issue(0, 0);
    issue(1, 1);

    for (int c = 0; c < ENCH; c++) {
        int s = c % NSTG;
        CP_WAIT1();      // groups <= c complete
        __syncthreads(); // visibility + protects stage s from next overwrite
        if (c + 2 < ENCH) issue(c + 2, (c + 2) % NSTG);
        uint32_t bA = base + s * EST, bB = base + (NSTG + s) * EST;
#pragma unroll
        for (int kk = 0; kk < 4; kk++) {
            uint32_t kb = kk * 32;
            uint32_t af[2][4];
#pragma unroll
            for (int ms = 0; ms < 2; ms++)
                LDSM4(af[ms][0], af[ms][1], af[ms][2], af[ms][3],
                      bA + aRow[ms] + (((uint32_t)colAl + kb) ^ aMask[ms]));
            uint32_t bf[8][2];
#pragma unroll
            for (int pp = 0; pp < 4; pp++)
                LDSM4(bf[2 * pp][0], bf[2 * pp][1], bf[2 * pp + 1][0], bf[2 * pp + 1][1],
                      bB + bRow[pp] + (((uint32_t)colBl + kb) ^ bMask[pp]));
#pragma unroll
            for (int ms = 0; ms < 2; ms++)
#pragma unroll
                for (int ns = 0; ns < 8; ns++)
                    mma_f16(d[ms][ns], af[ms][0], af[ms][1], af[ms][2], af[ms][3],
                            bf[ns][0], bf[ns][1]);
        }
    }

    // Epilogue: tanh + q-dot; reduce over cols (4 lanes) via shfl, warps via smem
#pragma unroll
    for (int ms = 0; ms < 2; ms++) {
        float pr0 = 0.f, pr1 = 0.f;
#pragma unroll
        for (int ns = 0; ns < 8; ns++) {
            int n0 = wn * 64 + ns * 8 + 2 * laneq;
            float q0 = qs[n0], q1 = qs[n0 + 1];
            pr0 += tanhf(d[ms][ns][0]) * q0 + tanhf(d[ms][ns][1]) * q1;
            pr1 += tanhf(d[ms][ns][2]) * q0 + tanhf(d[ms][ns][3]) * q1;
        }
#pragma unroll
        for (int o = 1; o < 4; o <<= 1) {
            pr0 += __shfl_xor_sync(0xffffffffu, pr0, o);
            pr1 += __shfl_xor_sync(0xffffffffu, pr1, o);
        }
        if (laneq == 0) {
            int r = wm * 32 + ms * 16 + lane4;
            red[wn * 128 + r] = pr0;
            red[wn * 128 + r + 8] = pr1;
        }
    }
    __syncthreads();
    if (tid < 128) {
        int t = t0 + tid;
        if (t < Tv)
            ebuf[(size_t)(b * Hv + h) * Tv + t] = red[tid] + red[128 + tid];
    }
}

// ---------------------------------------------------------------------------
// Masked softmax over T, in place. w = softmax(SCALING*e) on t<len, 0 else.
// ---------------------------------------------------------------------------
__global__ __launch_bounds__(256) void softmax_kernel(float* __restrict__ wbuf,
                                                      const int* __restrict__ lens) {
    int bh = blockIdx.x;
    int b = bh / Hv;
    int len = get_len(lens, b);
    int tid = threadIdx.x;
    __shared__ float s[Tv];
    __shared__ float red[16];
    float* row = wbuf + (size_t)bh * Tv;
    for (int t = tid; t < Tv; t += 256) s[t] = row[t];
    __syncthreads();

    float m = -1e30f;
    for (int t = tid; t < len; t += 256) m = fmaxf(m, s[t]);
#pragma unroll
    for (int o = 16; o; o >>= 1) m = fmaxf(m, __shfl_xor_sync(0xffffffffu, m, o));
    if ((tid & 31) == 0) red[tid >> 5] = m;
    __syncthreads();
    m = red[0];
#pragma unroll
    for (int i = 1; i < 8; i++) m = fmaxf(m, red[i]);
    float M = SCALING * m;

    float lsum = 0.f;
    for (int t = tid; t < len; t += 256) lsum += expf(SCALING * s[t] - M);
#pragma unroll
    for (int o = 16; o; o >>= 1) lsum += __shfl_xor_sync(0xffffffffu, lsum, o);
    if ((tid & 31) == 0) red[8 + (tid >> 5)] = lsum;
    __syncthreads();
    float total = 0.f;
#pragma unroll
    for (int i = 0; i < 8; i++) total += red[8 + i];
    float inv = 1.f / total;

    for (int t = tid; t < Tv; t += 256)
        row[t] = (t < len) ? expf(SCALING * s[t] - M) * inv : 0.f;
}

// ---------------------------------------------------------------------------
// u partials from fp16 enc: g_up[tc][b][h][d] = sum_t w[b,h,t]*enc16[b,t,d]
// Chunks beyond len write zero and skip all loads.
// ---------------------------------------------------------------------------
__global__ __launch_bounds__(256) void u_kernel(const float* __restrict__ wbuf,
                                                const int* __restrict__ lens) {
    int chunk = blockIdx.x, tc = blockIdx.y, b = blockIdx.z;
    int d = chunk * 256 + threadIdx.x;
    int len = get_len(lens, b);
    int t0 = tc * 128;
    if (t0 >= len) {
#pragma unroll
        for (int h = 0; h < Hv; h++)
            g_up[(((size_t)tc * Bv + b) * Hv + h) * Ev + d] = 0.f;
        return;
    }
    int tmax = min(min(128, Tv - t0), len - t0);
    __shared__ float ws[Hv][128];
    float acc[Hv] = {0.f, 0.f, 0.f, 0.f, 0.f, 0.f, 0.f, 0.f};
#pragma unroll
    for (int r = 0; r < 4; r++) {
        int f = r * 256 + threadIdx.x;
        int h = f >> 7, tt = f & 127;
        int t = t0 + tt;
        ws[h][tt] = (t < Tv) ? wbuf[((size_t)(b * Hv + h)) * Tv + t] : 0.f;
    }
    __syncthreads();
    const __half* A = g_enc16 + (size_t)b * Tv * Ev;
    for (int tt = 0; tt < tmax; tt++) {
        float x = __half2float(A[(size_t)(t0 + tt) * Ev + d]);
#pragma unroll
        for (int h = 0; h < Hv; h++) acc[h] += ws[h][tt] * x;
    }
#pragma unroll
    for (int h = 0; h < Hv; h++)
        g_up[(((size_t)tc * Bv + b) * Hv + h) * Ev + d] = acc[h];
}

// ---------------------------------------------------------------------------
// c[b,h,v] = u[b,h,:]·Wv[h,:,v]  (partials reduced inline)
// ---------------------------------------------------------------------------
__global__ __launch_bounds__(128) void c_kernel(const float* __restrict__ Wv) {
    int h = blockIdx.x, b = blockIdx.y;
    int v = threadIdx.x;
    __shared__ float us[Ev];
    for (int i = v; i < Ev; i += 128) {
        float s = 0.f;
#pragma unroll
        for (int tc = 0; tc < TCHUNK; tc++)
            s += g_up[(((size_t)tc * Bv + b) * Hv + h) * Ev + i];
        us[i] = s;
    }
    __syncthreads();
    float acc = 0.f;
    const float* W = Wv + (size_t)h * Ev * DVv + v;
#pragma unroll 8
    for (int d = 0; d < Ev; d++) acc += us[d] * W[(size_t)d * DVv];
    g_c[(b * Hv + h) * DVv + v] = acc;
}

// ---------------------------------------------------------------------------
// out[b,e] = c_flat[b,:]·Wo[:,e]
// ---------------------------------------------------------------------------
__global__ __launch_bounds__(256) void out_kernel(const float* __restrict__ Wo,
                                                  float* __restrict__ out) {
    int chunk = blockIdx.x, b = blockIdx.y;
    int e = chunk * 256 + threadIdx.x;
    __shared__ float cs[Hv * DVv];
    for (int i = threadIdx.x; i < Hv * DVv; i += 256) cs[i] = g_c[b * Hv * DVv + i];
    __syncthreads();
    float acc = 0.f;
#pragma unroll 8
    for (int i = 0; i < Hv * DVv; i++) acc += cs[i] * Wo[(size_t)i * Ev + e];
    out[(size_t)b * Ev + e] = acc;
}

// ---------------------------------------------------------------------------
extern "C" void kernel_launch(void* const* d_in, const int* in_sizes, int n_in,
                              void* d_out, int out_size) {
    const float* enc   = (const float*)d_in[0];
    const int*   lens  = (const int*)d_in[1];
    const float* dec_z = (const float*)d_in[2];
    const float* Wq    = (const float*)d_in[3];
    const float* bq    = (const float*)d_in[4];
    const float* Wk    = (const float*)d_in[5];
    const float* Wv    = (const float*)d_in[6];
    const float* Wo    = (const float*)d_in[7];

    float* out  = (float*)d_out;   // (B,E)
    float* wbuf = out + Bv * Ev;   // (B,H,T): e logits, then w in place

    static int smem_set = 0;
    if (!smem_set) {
        cudaFuncSetAttribute(e_tc_kernel, cudaFuncAttributeMaxDynamicSharedMemorySize, E_SMEM);
        smem_set = 1;
    }

    enc16_kernel<<<(Bv * Tv * Ev) / (256 * 8), 256>>>(enc);
    wkT16_kernel<<<dim3(Ev / 32, DKv / 32, Hv), 256>>>(Wk);
    q_kernel<<<dim3(Hv, Bv), 128>>>(dec_z, Wq, bq);
    e_tc_kernel<<<dim3(Hv, (Tv + 127) / 128, Bv), 256, E_SMEM>>>(wbuf);
    softmax_kernel<<<Bv * Hv, 256>>>(wbuf, lens);
    u_kernel<<<dim3(Ev / 256, TCHUNK, Bv), 256>>>(wbuf, lens);
    c_kernel<<<dim3(Hv, Bv), 128>>>(Wv);
    out_kernel<<<dim3(Ev / 256, Bv), 256>>>(Wo, out);
}

// round 7
// speedup vs baseline: 5.1645x; 1.1531x over previous
#include <cuda_runtime.h>
#include <cuda_fp16.h>
#include <cstdint>

#define Bv 32
#define Tv 1500
#define Ev 1024
#define Hv 8
#define DKv 128
#define DVv 128
#define Dv 1024
#define SCALING 0.088388347648318447f  // 1/sqrt(128)
#define TCHUNK 12

// Scratch (no allocations allowed)
__device__ float g_q[Bv * Hv * DKv];            // tanh(dec_z@Wq + bq)
__device__ float g_c[Bv * Hv * DVv];            // u @ Wv
__device__ float g_up[TCHUNK * Bv * Hv * Ev];   // u partials over t-chunks
__device__ __half g_enc16[(size_t)Bv * Tv * Ev];   // enc in fp16 (98.3 MB)
__device__ __half g_wkT16[(size_t)Hv * DKv * Ev];  // Wk^T in fp16: [h][n][e]

// ---------------------------------------------------------------------------
// PTX helpers (sm_80-level only; tcgen05 is rejected by this harness target)
// ---------------------------------------------------------------------------
__device__ __forceinline__ uint32_t smem_u32(const void* p) {
    uint32_t a;
    asm("{ .reg .u64 t; cvta.to.shared.u64 t, %1; cvt.u32.u64 %0, t; }" : "=r"(a) : "l"(p));
    return a;
}
#define CP16(sm, gm, sz) \
    asm volatile("cp.async.cg.shared.global [%0], [%1], 16, %2;" ::"r"(sm), "l"(gm), "r"(sz) : "memory")
#define CP_COMMIT() asm volatile("cp.async.commit_group;" ::: "memory")
#define CP_WAIT1() asm volatile("cp.async.wait_group 1;" ::: "memory")
#define LDSM4(r0, r1, r2, r3, a)                                             \
    asm volatile("ldmatrix.sync.aligned.m8n8.x4.shared.b16 {%0,%1,%2,%3}, [%4];" \
                 : "=r"(r0), "=r"(r1), "=r"(r2), "=r"(r3) : "r"(a))

__device__ __forceinline__ void mma_f16(float* d, uint32_t a0, uint32_t a1, uint32_t a2,
                                        uint32_t a3, uint32_t b0, uint32_t b1) {
    asm volatile(
        "mma.sync.aligned.m16n8k16.row.col.f32.f16.f16.f32 "
        "{%0,%1,%2,%3}, {%4,%5,%6,%7}, {%8,%9}, {%0,%1,%2,%3};"
        : "+f"(d[0]), "+f"(d[1]), "+f"(d[2]), "+f"(d[3])
        : "r"(a0), "r"(a1), "r"(a2), "r"(a3), "r"(b0), "r"(b1));
}
__device__ __forceinline__ uint32_t sw128(uint32_t o) { return o ^ ((o >> 3) & 0x70); }

// ---------------------------------------------------------------------------
// Length read with dtype sniff (int64 declared, int32 in practice)
// ---------------------------------------------------------------------------
__device__ __forceinline__ int get_len(const int* __restrict__ L, int b) {
    bool is64 = (L[1] == 0);
    return is64 ? L[2 * b] : L[b];
}

// ---------------------------------------------------------------------------
// enc -> fp16 (round-to-nearest), clipped to ceil128(len) rows per batch.
// Rows beyond the clip are never read (e-tiles skipped, u clipped).
// ---------------------------------------------------------------------------
__global__ __launch_bounds__(256) void enc16_kernel(const float* __restrict__ enc,
                                                    const int* __restrict__ lens) {
    size_t base = ((size_t)blockIdx.x * 256 + threadIdx.x) * 8;
    int t = (int)((base / Ev) % Tv);
    int b = (int)(base / ((size_t)Ev * Tv));
    int len = get_len(lens, b);
    if (t >= ((len + 127) & ~127)) return;
    float4 v0 = *(const float4*)(enc + base);
    float4 v1 = *(const float4*)(enc + base + 4);
    __half2 h[4];
    h[0] = __floats2half2_rn(v0.x, v0.y);
    h[1] = __floats2half2_rn(v0.z, v0.w);
    h[2] = __floats2half2_rn(v1.x, v1.y);
    h[3] = __floats2half2_rn(v1.z, v1.w);
    *(uint4*)(g_enc16 + base) = *(uint4*)h;
}

// ---------------------------------------------------------------------------
// wkT16[h][n][e] = fp16(Wk[h][e][n])
// ---------------------------------------------------------------------------
__global__ __launch_bounds__(256) void wkT16_kernel(const float* __restrict__ Wk) {
    __shared__ float tile[32][33];
    int e0 = blockIdx.x * 32, n0 = blockIdx.y * 32, h = blockIdx.z;
    int tx = threadIdx.x & 31, ty = threadIdx.x >> 5;
    for (int i = ty; i < 32; i += 8)
        tile[i][tx] = Wk[((size_t)h * Ev + e0 + i) * DKv + n0 + tx];
    __syncthreads();
    for (int i = ty; i < 32; i += 8)
        g_wkT16[((size_t)h * DKv + n0 + i) * Ev + e0 + tx] = __float2half_rn(tile[tx][i]);
}

// ---------------------------------------------------------------------------
// q[b,h,k] = tanh(dec_z[b,:]·Wq[h,:,k] + bq[h,k])
// ---------------------------------------------------------------------------
__global__ __launch_bounds__(128) void q_kernel(const float* __restrict__ dec_z,
                                                const float* __restrict__ Wq,
                                                const float* __restrict__ bq) {
    int h = blockIdx.x, b = blockIdx.y;
    int k = threadIdx.x;
    __shared__ float zs[Dv];
    for (int i = k; i < Dv; i += 128) zs[i] = dec_z[b * Dv + i];
    __syncthreads();
    float acc = bq[h * DKv + k];
    const float* W = Wq + (size_t)h * Dv * DKv + k;
#pragma unroll 8
    for (int d = 0; d < Dv; d++) acc += zs[d] * W[(size_t)d * DKv];
    g_q[(b * Hv + h) * DKv + k] = tanhf(acc);
}

// ---------------------------------------------------------------------------
// e[b,h,t] = sum_n tanh( (enc@Wk[h])[t,n] ) * q[b,h,n]
// fp16 m16n8k16 GEMM: per CTA = (h, 128-t tile, b). Tiles with t0 >= len
// exit immediately (their logits are masked to 0 by softmax anyway).
// 3-stage cp.async ring, precomputed swizzled addrs, ldmatrix.x4 fragments.
// ---------------------------------------------------------------------------
#define ECH 64                 // K halves per stage (128 B per row)
#define ENCH (Ev / ECH)        // 16 chunks
#define EST 16384              // one tile stage: 128 rows * 128 B
#define NSTG 3
#define OFF_QS (2 * NSTG * EST)          // 98304
#define OFF_RED (OFF_QS + 512)
#define E_SMEM (OFF_RED + 1024)          // 99840 (x2 CTAs fits 228KB)

__global__ __launch_bounds__(256, 2) void e_tc_kernel(float* __restrict__ ebuf,
                                                      const int* __restrict__ lens) {
    extern __shared__ __align__(16) char dsm[];
    float* qs = (float*)(dsm + OFF_QS);
    float* red = (float*)(dsm + OFF_RED);  // [2][128]

    int tid = threadIdx.x, wid = tid >> 5, lane = tid & 31;
    int h = blockIdx.x, tile = blockIdx.y, b = blockIdx.z;
    int t0 = tile * 128;
    int len = get_len(lens, b);
    if (t0 >= len) return;  // dead tile: softmax writes 0 over this range

    int wm = wid & 3, wn = wid >> 2;
    int lane4 = lane >> 2, laneq = lane & 3;

    if (tid < DKv) qs[tid] = g_q[(b * Hv + h) * DKv + tid];

    const __half* A = g_enc16 + (size_t)b * Tv * Ev;
    const __half* Wt = g_wkT16 + (size_t)h * DKv * Ev;

    uint32_t base = smem_u32(dsm);
    // stage s: A at base + s*EST, B at base + (NSTG+s)*EST

    // ---- precomputed store-side addresses (4 rounds per tile) ----
    uint32_t swz[4];
    const __half* pA[4];
    const __half* pB[4];
    uint32_t szA[4];
#pragma unroll
    for (int r = 0; r < 4; r++) {
        int idx = r * 256 + tid;
        int row = idx >> 3, seg = idx & 7;
        swz[r] = sw128(row * 128 + seg * 16);
        int t = t0 + row;
        szA[r] = (t < Tv) ? 16u : 0u;
        pA[r] = A + (size_t)t * Ev + seg * 8;
        pB[r] = Wt + (size_t)row * Ev + seg * 8;
    }

    auto issue = [&](int c, int s) {
        int k0 = c * ECH;
        uint32_t bA = base + s * EST, bB = base + (NSTG + s) * EST;
#pragma unroll
        for (int r = 0; r < 4; r++) CP16(bA + swz[r], pA[r] + k0, szA[r]);
#pragma unroll
        for (int r = 0; r < 4; r++) CP16(bB + swz[r], pB[r] + k0, 16u);
        CP_COMMIT();
    };

    // ---- precomputed ldmatrix-side row terms + swizzle masks ----
    int rowAl = (lane & 7) + ((lane >> 3) & 1) * 8;
    int colAl = ((lane >> 4) & 1) * 16;
    int rowBl = (lane & 7) + ((lane >> 4) & 1) * 8;
    int colBl = ((lane >> 3) & 1) * 16;
    uint32_t aRow[2], aMask[2];
#pragma unroll
    for (int ms = 0; ms < 2; ms++) {
        int row = wm * 32 + ms * 16 + rowAl;
        aRow[ms] = row * 128;
        aMask[ms] = (row & 7) << 4;
    }
    uint32_t bRow[4], bMask[4];
#pragma unroll
    for (int pp = 0; pp < 4; pp++) {
        int row = wn * 64 + pp * 16 + rowBl;
        bRow[pp] = row * 128;
        bMask[pp] = (row & 7) << 4;
    }

    float d[2][8][4];
#pragma unroll
    for (int ms = 0; ms < 2; ms++)
#pragma unroll
        for (int ns = 0; ns < 8; ns++)
#pragma unroll
            for (int j = 0; j < 4; j++) d[ms][ns][j] = 0.f;

    issue(0, 0);
    issue(1, 1);

    for (int c = 0; c < ENCH; c++) {
        int s = c % NSTG;
        CP_WAIT1();      // groups <= c complete
        __syncthreads(); // visibility + protects stage s from next overwrite
        if (c + 2 < ENCH) issue(c + 2, (c + 2) % NSTG);
        uint32_t bA = base + s * EST, bB = base + (NSTG + s) * EST;
#pragma unroll
        for (int kk = 0; kk < 4; kk++) {
            uint32_t kb = kk * 32;
            uint32_t af[2][4];
#pragma unroll
            for (int ms = 0; ms < 2; ms++)
                LDSM4(af[ms][0], af[ms][1], af[ms][2], af[ms][3],
                      bA + aRow[ms] + (((uint32_t)colAl + kb) ^ aMask[ms]));
            uint32_t bf[8][2];
#pragma unroll
            for (int pp = 0; pp < 4; pp++)
                LDSM4(bf[2 * pp][0], bf[2 * pp][1], bf[2 * pp + 1][0], bf[2 * pp + 1][1],
                      bB + bRow[pp] + (((uint32_t)colBl + kb) ^ bMask[pp]));
#pragma unroll
            for (int ms = 0; ms < 2; ms++)
#pragma unroll
                for (int ns = 0; ns < 8; ns++)
                    mma_f16(d[ms][ns], af[ms][0], af[ms][1], af[ms][2], af[ms][3],
                            bf[ns][0], bf[ns][1]);
        }
    }

    // Epilogue: tanh + q-dot; reduce over cols (4 lanes) via shfl, warps via smem
#pragma unroll
    for (int ms = 0; ms < 2; ms++) {
        float pr0 = 0.f, pr1 = 0.f;
#pragma unroll
        for (int ns = 0; ns < 8; ns++) {
            int n0 = wn * 64 + ns * 8 + 2 * laneq;
            float q0 = qs[n0], q1 = qs[n0 + 1];
            pr0 += tanhf(d[ms][ns][0]) * q0 + tanhf(d[ms][ns][1]) * q1;
            pr1 += tanhf(d[ms][ns][2]) * q0 + tanhf(d[ms][ns][3]) * q1;
        }
#pragma unroll
        for (int o = 1; o < 4; o <<= 1) {
            pr0 += __shfl_xor_sync(0xffffffffu, pr0, o);
            pr1 += __shfl_xor_sync(0xffffffffu, pr1, o);
        }
        if (laneq == 0) {
            int r = wm * 32 + ms * 16 + lane4;
            red[wn * 128 + r] = pr0;
            red[wn * 128 + r + 8] = pr1;
        }
    }
    __syncthreads();
    if (tid < 128) {
        int t = t0 + tid;
        if (t < Tv)
            ebuf[(size_t)(b * Hv + h) * Tv + t] = red[tid] + red[128 + tid];
    }
}

// ---------------------------------------------------------------------------
// Masked softmax over T, in place. w = softmax(SCALING*e) on t<len, 0 else.
// (Writes the full T range, overwriting poison in skipped-tile regions.)
// ---------------------------------------------------------------------------
__global__ __launch_bounds__(256) void softmax_kernel(float* __restrict__ wbuf,
                                                      const int* __restrict__ lens) {
    int bh = blockIdx.x;
    int b = bh / Hv;
    int len = get_len(lens, b);
    int tid = threadIdx.x;
    __shared__ float s[Tv];
    __shared__ float red[16];
    float* row = wbuf + (size_t)bh * Tv;
    for (int t = tid; t < Tv; t += 256) s[t] = row[t];
    __syncthreads();

    float m = -1e30f;
    for (int t = tid; t < len; t += 256) m = fmaxf(m, s[t]);
#pragma unroll
    for (int o = 16; o; o >>= 1) m = fmaxf(m, __shfl_xor_sync(0xffffffffu, m, o));
    if ((tid & 31) == 0) red[tid >> 5] = m;
    __syncthreads();
    m = red[0];
#pragma unroll
    for (int i = 1; i < 8; i++) m = fmaxf(m, red[i]);
    float M = SCALING * m;

    float lsum = 0.f;
    for (int t = tid; t < len; t += 256) lsum += expf(SCALING * s[t] - M);
#pragma unroll
    for (int o = 16; o; o >>= 1) lsum += __shfl_xor_sync(0xffffffffu, lsum, o);
    if ((tid & 31) == 0) red[8 + (tid >> 5)] = lsum;
    __syncthreads();
    float total = 0.f;
#pragma unroll
    for (int i = 0; i < 8; i++) total += red[8 + i];
    float inv = 1.f / total;

    for (int t = tid; t < Tv; t += 256)
        row[t] = (t < len) ? expf(SCALING * s[t] - M) * inv : 0.f;
}

// ---------------------------------------------------------------------------
// u partials from fp16 enc: g_up[tc][b][h][d] = sum_t w[b,h,t]*enc16[b,t,d]
// Chunks beyond len write zero and skip all loads.
// ---------------------------------------------------------------------------
__global__ __launch_bounds__(256) void u_kernel(const float* __restrict__ wbuf,
                                                const int* __restrict__ lens) {
    int chunk = blockIdx.x, tc = blockIdx.y, b = blockIdx.z;
    int d = chunk * 256 + threadIdx.x;
    int len = get_len(lens, b);
    int t0 = tc * 128;
    if (t0 >= len) {
#pragma unroll
        for (int h = 0; h < Hv; h++)
            g_up[(((size_t)tc * Bv + b) * Hv + h) * Ev + d] = 0.f;
        return;
    }
    int tmax = min(min(128, Tv - t0), len - t0);
    __shared__ float ws[Hv][128];
    float acc[Hv] = {0.f, 0.f, 0.f, 0.f, 0.f, 0.f, 0.f, 0.f};
#pragma unroll
    for (int r = 0; r < 4; r++) {
        int f = r * 256 + threadIdx.x;
        int h = f >> 7, tt = f & 127;
        int t = t0 + tt;
        ws[h][tt] = (t < Tv) ? wbuf[((size_t)(b * Hv + h)) * Tv + t] : 0.f;
    }
    __syncthreads();
    const __half* A = g_enc16 + (size_t)b * Tv * Ev;
    for (int tt = 0; tt < tmax; tt++) {
        float x = __half2float(A[(size_t)(t0 + tt) * Ev + d]);
#pragma unroll
        for (int h = 0; h < Hv; h++) acc[h] += ws[h][tt] * x;
    }
#pragma unroll
    for (int h = 0; h < Hv; h++)
        g_up[(((size_t)tc * Bv + b) * Hv + h) * Ev + d] = acc[h];
}

// ---------------------------------------------------------------------------
// c[b,h,v] = u[b,h,:]·Wv[h,:,v]  (partials reduced inline)
// ---------------------------------------------------------------------------
__global__ __launch_bounds__(128) void c_kernel(const float* __restrict__ Wv) {
    int h = blockIdx.x, b = blockIdx.y;
    int v = threadIdx.x;
    __shared__ float us[Ev];
    for (int i = v; i < Ev; i += 128) {
        float s = 0.f;
#pragma unroll
        for (int tc = 0; tc < TCHUNK; tc++)
            s += g_up[(((size_t)tc * Bv + b) * Hv + h) * Ev + i];
        us[i] = s;
    }
    __syncthreads();
    float acc = 0.f;
    const float* W = Wv + (size_t)h * Ev * DVv + v;
#pragma unroll 8
    for (int d = 0; d < Ev; d++) acc += us[d] * W[(size_t)d * DVv];
    g_c[(b * Hv + h) * DVv + v] = acc;
}

// ---------------------------------------------------------------------------
// out[b,e] = c_flat[b,:]·Wo[:,e]
// ---------------------------------------------------------------------------
__global__ __launch_bounds__(256) void out_kernel(const float* __restrict__ Wo,
                                                  float* __restrict__ out) {
    int chunk = blockIdx.x, b = blockIdx.y;
    int e = chunk * 256 + threadIdx.x;
    __shared__ float cs[Hv * DVv];
    for (int i = threadIdx.x; i < Hv * DVv; i += 256) cs[i] = g_c[b * Hv * DVv + i];
    __syncthreads();
    float acc = 0.f;
#pragma unroll 8
    for (int i = 0; i < Hv * DVv; i++) acc += cs[i] * Wo[(size_t)i * Ev + e];
    out[(size_t)b * Ev + e] = acc;
}

// ---------------------------------------------------------------------------
extern "C" void kernel_launch(void* const* d_in, const int* in_sizes, int n_in,
                              void* d_out, int out_size) {
    const float* enc   = (const float*)d_in[0];
    const int*   lens  = (const int*)d_in[1];
    const float* dec_z = (const float*)d_in[2];
    const float* Wq    = (const float*)d_in[3];
    const float* bq    = (const float*)d_in[4];
    const float* Wk    = (const float*)d_in[5];
    const float* Wv    = (const float*)d_in[6];
    const float* Wo    = (const float*)d_in[7];

    float* out  = (float*)d_out;   // (B,E)
    float* wbuf = out + Bv * Ev;   // (B,H,T): e logits, then w in place

    static int smem_set = 0;
    if (!smem_set) {
        cudaFuncSetAttribute(e_tc_kernel, cudaFuncAttributeMaxDynamicSharedMemorySize, E_SMEM);
        smem_set = 1;
    }

    enc16_kernel<<<(Bv * Tv * Ev) / (256 * 8), 256>>>(enc, lens);
    wkT16_kernel<<<dim3(Ev / 32, DKv / 32, Hv), 256>>>(Wk);
    q_kernel<<<dim3(Hv, Bv), 128>>>(dec_z, Wq, bq);
    e_tc_kernel<<<dim3(Hv, (Tv + 127) / 128, Bv), 256, E_SMEM>>>(wbuf, lens);
    softmax_kernel<<<Bv * Hv, 256>>>(wbuf, lens);
    u_kernel<<<dim3(Ev / 256, TCHUNK, Bv), 256>>>(wbuf, lens);
    c_kernel<<<dim3(Hv, Bv), 128>>>(Wv);
    out_kernel<<<dim3(Ev / 256, Bv), 256>>>(Wo, out);
}

// round 8
// speedup vs baseline: 5.5050x; 1.0659x over previous
#include <cuda_runtime.h>
#include <cuda_fp16.h>
#include <cstdint>

#define Bv 32
#define Tv 1500
#define Ev 1024
#define Hv 8
#define DKv 128
#define DVv 128
#define Dv 1024
#define SCALING 0.088388347648318447f  // 1/sqrt(128)
#define TCHUNK 12

// Scratch (no allocations allowed)
__device__ float g_q[Bv * Hv * DKv];            // tanh(dec_z@Wq + bq)
__device__ float g_c[Bv * Hv * DVv];            // u @ Wv
__device__ float g_up[TCHUNK * Bv * Hv * Ev];   // u partials over t-chunks
__device__ __half g_enc16[(size_t)Bv * Tv * Ev];   // enc in fp16 (98.3 MB)
__device__ __half g_wkT16[(size_t)Hv * DKv * Ev];  // Wk^T in fp16: [h][n][e]

// ---------------------------------------------------------------------------
// PTX helpers (sm_80-level only; tcgen05 is rejected by this harness target)
// ---------------------------------------------------------------------------
__device__ __forceinline__ uint32_t smem_u32(const void* p) {
    uint32_t a;
    asm("{ .reg .u64 t; cvta.to.shared.u64 t, %1; cvt.u32.u64 %0, t; }" : "=r"(a) : "l"(p));
    return a;
}
#define CP16(sm, gm, sz) \
    asm volatile("cp.async.cg.shared.global [%0], [%1], 16, %2;" ::"r"(sm), "l"(gm), "r"(sz) : "memory")
#define CP_COMMIT() asm volatile("cp.async.commit_group;" ::: "memory")
#define CP_WAIT1() asm volatile("cp.async.wait_group 1;" ::: "memory")
#define LDSM4(r0, r1, r2, r3, a)                                             \
    asm volatile("ldmatrix.sync.aligned.m8n8.x4.shared.b16 {%0,%1,%2,%3}, [%4];" \
                 : "=r"(r0), "=r"(r1), "=r"(r2), "=r"(r3) : "r"(a))

__device__ __forceinline__ void mma_f16(float* d, uint32_t a0, uint32_t a1, uint32_t a2,
                                        uint32_t a3, uint32_t b0, uint32_t b1) {
    asm volatile(
        "mma.sync.aligned.m16n8k16.row.col.f32.f16.f16.f32 "
        "{%0,%1,%2,%3}, {%4,%5,%6,%7}, {%8,%9}, {%0,%1,%2,%3};"
        : "+f"(d[0]), "+f"(d[1]), "+f"(d[2]), "+f"(d[3])
        : "r"(a0), "r"(a1), "r"(a2), "r"(a3), "r"(b0), "r"(b1));
}
__device__ __forceinline__ uint32_t sw128(uint32_t o) { return o ^ ((o >> 3) & 0x70); }

// ---------------------------------------------------------------------------
// Length read with dtype sniff (int64 declared, int32 in practice)
// ---------------------------------------------------------------------------
__device__ __forceinline__ int get_len(const int* __restrict__ L, int b) {
    bool is64 = (L[1] == 0);
    return is64 ? L[2 * b] : L[b];
}

// ---------------------------------------------------------------------------
// enc -> fp16 (round-to-nearest), clipped to ceil128(len) rows per batch.
// ---------------------------------------------------------------------------
__global__ __launch_bounds__(256) void enc16_kernel(const float* __restrict__ enc,
                                                    const int* __restrict__ lens) {
    size_t base = ((size_t)blockIdx.x * 256 + threadIdx.x) * 8;
    int t = (int)((base / Ev) % Tv);
    int b = (int)(base / ((size_t)Ev * Tv));
    int len = get_len(lens, b);
    if (t >= ((len + 127) & ~127)) return;
    float4 v0 = *(const float4*)(enc + base);
    float4 v1 = *(const float4*)(enc + base + 4);
    __half2 h[4];
    h[0] = __floats2half2_rn(v0.x, v0.y);
    h[1] = __floats2half2_rn(v0.z, v0.w);
    h[2] = __floats2half2_rn(v1.x, v1.y);
    h[3] = __floats2half2_rn(v1.z, v1.w);
    *(uint4*)(g_enc16 + base) = *(uint4*)h;
}

// ---------------------------------------------------------------------------
// wkT16[h][n][e] = fp16(Wk[h][e][n])
// ---------------------------------------------------------------------------
__global__ __launch_bounds__(256) void wkT16_kernel(const float* __restrict__ Wk) {
    __shared__ float tile[32][33];
    int e0 = blockIdx.x * 32, n0 = blockIdx.y * 32, h = blockIdx.z;
    int tx = threadIdx.x & 31, ty = threadIdx.x >> 5;
    for (int i = ty; i < 32; i += 8)
        tile[i][tx] = Wk[((size_t)h * Ev + e0 + i) * DKv + n0 + tx];
    __syncthreads();
    for (int i = ty; i < 32; i += 8)
        g_wkT16[((size_t)h * DKv + n0 + i) * Ev + e0 + tx] = __float2half_rn(tile[tx][i]);
}

// ---------------------------------------------------------------------------
// q[b,h,k] = tanh(dec_z[b,:]·Wq[h,:,k] + bq[h,k])   (2-way split acc chain)
// ---------------------------------------------------------------------------
__global__ __launch_bounds__(128) void q_kernel(const float* __restrict__ dec_z,
                                                const float* __restrict__ Wq,
                                                const float* __restrict__ bq) {
    int h = blockIdx.x, b = blockIdx.y;
    int k = threadIdx.x;
    __shared__ float zs[Dv];
    for (int i = k; i < Dv; i += 128) zs[i] = dec_z[b * Dv + i];
    __syncthreads();
    float a0 = bq[h * DKv + k], a1 = 0.f;
    const float* W = Wq + (size_t)h * Dv * DKv + k;
#pragma unroll 8
    for (int d = 0; d < Dv; d += 2) {
        a0 += zs[d] * W[(size_t)d * DKv];
        a1 += zs[d + 1] * W[(size_t)(d + 1) * DKv];
    }
    g_q[(b * Hv + h) * DKv + k] = tanhf(a0 + a1);
}

// ---------------------------------------------------------------------------
// e[b,h,t] = sum_n tanh( (enc@Wk[h])[t,n] ) * q[b,h,n]
// fp16 m16n8k16 GEMM: per CTA = (h, 128-t tile, b); t0 >= len tiles exit.
// 3-stage cp.async ring, precomputed swizzled addrs, ldmatrix.x4 fragments.
// ---------------------------------------------------------------------------
#define ECH 64                 // K halves per stage (128 B per row)
#define ENCH (Ev / ECH)        // 16 chunks
#define EST 16384              // one tile stage: 128 rows * 128 B
#define NSTG 3
#define OFF_QS (2 * NSTG * EST)          // 98304
#define OFF_RED (OFF_QS + 512)
#define E_SMEM (OFF_RED + 1024)          // 99840 (x2 CTAs fits 228KB)

__global__ __launch_bounds__(256, 2) void e_tc_kernel(float* __restrict__ ebuf,
                                                      const int* __restrict__ lens) {
    extern __shared__ __align__(16) char dsm[];
    float* qs = (float*)(dsm + OFF_QS);
    float* red = (float*)(dsm + OFF_RED);  // [2][128]

    int tid = threadIdx.x, wid = tid >> 5, lane = tid & 31;
    int h = blockIdx.x, tile = blockIdx.y, b = blockIdx.z;
    int t0 = tile * 128;
    int len = get_len(lens, b);
    if (t0 >= len) return;  // dead tile: softmax writes 0 over this range

    int wm = wid & 3, wn = wid >> 2;
    int lane4 = lane >> 2, laneq = lane & 3;

    if (tid < DKv) qs[tid] = g_q[(b * Hv + h) * DKv + tid];

    const __half* A = g_enc16 + (size_t)b * Tv * Ev;
    const __half* Wt = g_wkT16 + (size_t)h * DKv * Ev;

    uint32_t base = smem_u32(dsm);

    uint32_t swz[4];
    const __half* pA[4];
    const __half* pB[4];
    uint32_t szA[4];
#pragma unroll
    for (int r = 0; r < 4; r++) {
        int idx = r * 256 + tid;
        int row = idx >> 3, seg = idx & 7;
        swz[r] = sw128(row * 128 + seg * 16);
        int t = t0 + row;
        szA[r] = (t < Tv) ? 16u : 0u;
        pA[r] = A + (size_t)t * Ev + seg * 8;
        pB[r] = Wt + (size_t)row * Ev + seg * 8;
    }

    auto issue = [&](int c, int s) {
        int k0 = c * ECH;
        uint32_t bA = base + s * EST, bB = base + (NSTG + s) * EST;
#pragma unroll
        for (int r = 0; r < 4; r++) CP16(bA + swz[r], pA[r] + k0, szA[r]);
#pragma unroll
        for (int r = 0; r < 4; r++) CP16(bB + swz[r], pB[r] + k0, 16u);
        CP_COMMIT();
    };

    int rowAl = (lane & 7) + ((lane >> 3) & 1) * 8;
    int colAl = ((lane >> 4) & 1) * 16;
    int rowBl = (lane & 7) + ((lane >> 4) & 1) * 8;
    int colBl = ((lane >> 3) & 1) * 16;
    uint32_t aRow[2], aMask[2];
#pragma unroll
    for (int ms = 0; ms < 2; ms++) {
        int row = wm * 32 + ms * 16 + rowAl;
        aRow[ms] = row * 128;
        aMask[ms] = (row & 7) << 4;
    }
    uint32_t bRow[4], bMask[4];
#pragma unroll
    for (int pp = 0; pp < 4; pp++) {
        int row = wn * 64 + pp * 16 + rowBl;
        bRow[pp] = row * 128;
        bMask[pp] = (row & 7) << 4;
    }

    float d[2][8][4];
#pragma unroll
    for (int ms = 0; ms < 2; ms++)
#pragma unroll
        for (int ns = 0; ns < 8; ns++)
#pragma unroll
            for (int j = 0; j < 4; j++) d[ms][ns][j] = 0.f;

    issue(0, 0);
    issue(1, 1);

    for (int c = 0; c < ENCH; c++) {
        int s = c % NSTG;
        CP_WAIT1();
        __syncthreads();
        if (c + 2 < ENCH) issue(c + 2, (c + 2) % NSTG);
        uint32_t bA = base + s * EST, bB = base + (NSTG + s) * EST;
#pragma unroll
        for (int kk = 0; kk < 4; kk++) {
            uint32_t kb = kk * 32;
            uint32_t af[2][4];
#pragma unroll
            for (int ms = 0; ms < 2; ms++)
                LDSM4(af[ms][0], af[ms][1], af[ms][2], af[ms][3],
                      bA + aRow[ms] + (((uint32_t)colAl + kb) ^ aMask[ms]));
            uint32_t bf[8][2];
#pragma unroll
            for (int pp = 0; pp < 4; pp++)
                LDSM4(bf[2 * pp][0], bf[2 * pp][1], bf[2 * pp + 1][0], bf[2 * pp + 1][1],
                      bB + bRow[pp] + (((uint32_t)colBl + kb) ^ bMask[pp]));
#pragma unroll
            for (int ms = 0; ms < 2; ms++)
#pragma unroll
                for (int ns = 0; ns < 8; ns++)
                    mma_f16(d[ms][ns], af[ms][0], af[ms][1], af[ms][2], af[ms][3],
                            bf[ns][0], bf[ns][1]);
        }
    }

    // Epilogue: tanh + q-dot; reduce over cols (4 lanes) via shfl, warps via smem
#pragma unroll
    for (int ms = 0; ms < 2; ms++) {
        float pr0 = 0.f, pr1 = 0.f;
#pragma unroll
        for (int ns = 0; ns < 8; ns++) {
            int n0 = wn * 64 + ns * 8 + 2 * laneq;
            float q0 = qs[n0], q1 = qs[n0 + 1];
            pr0 += tanhf(d[ms][ns][0]) * q0 + tanhf(d[ms][ns][1]) * q1;
            pr1 += tanhf(d[ms][ns][2]) * q0 + tanhf(d[ms][ns][3]) * q1;
        }
#pragma unroll
        for (int o = 1; o < 4; o <<= 1) {
            pr0 += __shfl_xor_sync(0xffffffffu, pr0, o);
            pr1 += __shfl_xor_sync(0xffffffffu, pr1, o);
        }
        if (laneq == 0) {
            int r = wm * 32 + ms * 16 + lane4;
            red[wn * 128 + r] = pr0;
            red[wn * 128 + r + 8] = pr1;
        }
    }
    __syncthreads();
    if (tid < 128) {
        int t = t0 + tid;
        if (t < Tv)
            ebuf[(size_t)(b * Hv + h) * Tv + t] = red[tid] + red[128 + tid];
    }
}

// ---------------------------------------------------------------------------
// Masked softmax over T, in place. w = softmax(SCALING*e) on t<len, 0 else.
// ---------------------------------------------------------------------------
__global__ __launch_bounds__(256) void softmax_kernel(float* __restrict__ wbuf,
                                                      const int* __restrict__ lens) {
    int bh = blockIdx.x;
    int b = bh / Hv;
    int len = get_len(lens, b);
    int tid = threadIdx.x;
    __shared__ float s[Tv];
    __shared__ float red[16];
    float* row = wbuf + (size_t)bh * Tv;
    for (int t = tid; t < Tv; t += 256) s[t] = row[t];
    __syncthreads();

    float m = -1e30f;
    for (int t = tid; t < len; t += 256) m = fmaxf(m, s[t]);
#pragma unroll
    for (int o = 16; o; o >>= 1) m = fmaxf(m, __shfl_xor_sync(0xffffffffu, m, o));
    if ((tid & 31) == 0) red[tid >> 5] = m;
    __syncthreads();
    m = red[0];
#pragma unroll
    for (int i = 1; i < 8; i++) m = fmaxf(m, red[i]);
    float M = SCALING * m;

    float lsum = 0.f;
    for (int t = tid; t < len; t += 256) lsum += expf(SCALING * s[t] - M);
#pragma unroll
    for (int o = 16; o; o >>= 1) lsum += __shfl_xor_sync(0xffffffffu, lsum, o);
    if ((tid & 31) == 0) red[8 + (tid >> 5)] = lsum;
    __syncthreads();
    float total = 0.f;
#pragma unroll
    for (int i = 0; i < 8; i++) total += red[8 + i];
    float inv = 1.f / total;

    for (int t = tid; t < Tv; t += 256)
        row[t] = (t < len) ? expf(SCALING * s[t] - M) * inv : 0.f;
}

// ---------------------------------------------------------------------------
// u partials, vectorized: each thread owns 4 consecutive d (one uint2/t),
// 32 FMA per 8B load; ws broadcasts amortized over 4 d. Same t-order per d
// as before -> bit-identical accumulation.
// ---------------------------------------------------------------------------
__global__ __launch_bounds__(256) void u_kernel(const float* __restrict__ wbuf,
                                                const int* __restrict__ lens) {
    int tc = blockIdx.x, b = blockIdx.y;
    int d0 = threadIdx.x * 4;
    int len = get_len(lens, b);
    int t0 = tc * 128;
    float* up = g_up + (((size_t)tc * Bv + b) * Hv) * Ev + d0;
    if (t0 >= len) {
#pragma unroll
        for (int h = 0; h < Hv; h++)
            *(float4*)(up + (size_t)h * Ev) = make_float4(0.f, 0.f, 0.f, 0.f);
        return;
    }
    int tmax = min(min(128, Tv - t0), len - t0);
    __shared__ float ws[Hv][128];
#pragma unroll
    for (int r = 0; r < 4; r++) {
        int f = r * 256 + threadIdx.x;
        int h = f >> 7, tt = f & 127;
        int t = t0 + tt;
        ws[h][tt] = (t < Tv) ? wbuf[((size_t)(b * Hv + h)) * Tv + t] : 0.f;
    }
    __syncthreads();

    float acc[Hv][4];
#pragma unroll
    for (int h = 0; h < Hv; h++)
#pragma unroll
        for (int j = 0; j < 4; j++) acc[h][j] = 0.f;

    const __half* A = g_enc16 + (size_t)b * Tv * Ev + (size_t)t0 * Ev + d0;
#pragma unroll 2
    for (int tt = 0; tt < tmax; tt++) {
        uint2 raw = *(const uint2*)(A + (size_t)tt * Ev);
        float2 x01 = __half22float2(*(__half2*)&raw.x);
        float2 x23 = __half22float2(*(__half2*)&raw.y);
#pragma unroll
        for (int h = 0; h < Hv; h++) {
            float w = ws[h][tt];
            acc[h][0] += w * x01.x;
            acc[h][1] += w * x01.y;
            acc[h][2] += w * x23.x;
            acc[h][3] += w * x23.y;
        }
    }
#pragma unroll
    for (int h = 0; h < Hv; h++)
        *(float4*)(up + (size_t)h * Ev) =
            make_float4(acc[h][0], acc[h][1], acc[h][2], acc[h][3]);
}

// ---------------------------------------------------------------------------
// c[b,h,v] = u[b,h,:]·Wv[h,:,v]  (partials reduced inline)
// ---------------------------------------------------------------------------
__global__ __launch_bounds__(128) void c_kernel(const float* __restrict__ Wv) {
    int h = blockIdx.x, b = blockIdx.y;
    int v = threadIdx.x;
    __shared__ float us[Ev];
    for (int i = v; i < Ev; i += 128) {
        float s = 0.f;
#pragma unroll
        for (int tc = 0; tc < TCHUNK; tc++)
            s += g_up[(((size_t)tc * Bv + b) * Hv + h) * Ev + i];
        us[i] = s;
    }
    __syncthreads();
    float acc = 0.f;
    const float* W = Wv + (size_t)h * Ev * DVv + v;
#pragma unroll 8
    for (int d = 0; d < Ev; d++) acc += us[d] * W[(size_t)d * DVv];
    g_c[(b * Hv + h) * DVv + v] = acc;
}

// ---------------------------------------------------------------------------
// out[b,e] = c_flat[b,:]·Wo[:,e]
// ---------------------------------------------------------------------------
__global__ __launch_bounds__(256) void out_kernel(const float* __restrict__ Wo,
                                                  float* __restrict__ out) {
    int chunk = blockIdx.x, b = blockIdx.y;
    int e = chunk * 256 + threadIdx.x;
    __shared__ float cs[Hv * DVv];
    for (int i = threadIdx.x; i < Hv * DVv; i += 256) cs[i] = g_c[b * Hv * DVv + i];
    __syncthreads();
    float acc = 0.f;
#pragma unroll 8
    for (int i = 0; i < Hv * DVv; i++) acc += cs[i] * Wo[(size_t)i * Ev + e];
    out[(size_t)b * Ev + e] = acc;
}

// ---------------------------------------------------------------------------
extern "C" void kernel_launch(void* const* d_in, const int* in_sizes, int n_in,
                              void* d_out, int out_size) {
    const float* enc   = (const float*)d_in[0];
    const int*   lens  = (const int*)d_in[1];
    const float* dec_z = (const float*)d_in[2];
    const float* Wq    = (const float*)d_in[3];
    const float* bq    = (const float*)d_in[4];
    const float* Wk    = (const float*)d_in[5];
    const float* Wv    = (const float*)d_in[6];
    const float* Wo    = (const float*)d_in[7];

    float* out  = (float*)d_out;   // (B,E)
    float* wbuf = out + Bv * Ev;   // (B,H,T): e logits, then w in place

    static int smem_set = 0;
    if (!smem_set) {
        cudaFuncSetAttribute(e_tc_kernel, cudaFuncAttributeMaxDynamicSharedMemorySize, E_SMEM);
        smem_set = 1;
    }

    enc16_kernel<<<(Bv * Tv * Ev) / (256 * 8), 256>>>(enc, lens);
    wkT16_kernel<<<dim3(Ev / 32, DKv / 32, Hv), 256>>>(Wk);
    q_kernel<<<dim3(Hv, Bv), 128>>>(dec_z, Wq, bq);
    e_tc_kernel<<<dim3(Hv, (Tv + 127) / 128, Bv), 256, E_SMEM>>>(wbuf, lens);
    softmax_kernel<<<Bv * Hv, 256>>>(wbuf, lens);
    u_kernel<<<dim3(TCHUNK, Bv), 256>>>(wbuf, lens);
    c_kernel<<<dim3(Hv, Bv), 128>>>(Wv);
    out_kernel<<<dim3(Ev / 256, Bv), 256>>>(Wo, out);
}

// round 9
// speedup vs baseline: 5.8851x; 1.0690x over previous
#include <cuda_runtime.h>
#include <cuda_fp16.h>
#include <cstdint>

#define Bv 32
#define Tv 1500
#define Ev 1024
#define Hv 8
#define DKv 128
#define DVv 128
#define Dv 1024
#define SCALING 0.088388347648318447f  // 1/sqrt(128)
#define TCHUNK 12

// Scratch (no allocations allowed)
__device__ float g_q[Bv * Hv * DKv];            // tanh(dec_z@Wq + bq)
__device__ float g_c[Bv * Hv * DVv];            // u @ Wv
__device__ float g_up[TCHUNK * Bv * Hv * Ev];   // u partials over t-chunks
__device__ __half g_enc16[(size_t)Bv * Tv * Ev];   // enc in fp16 (98.3 MB)
__device__ __half g_wkT16[(size_t)Hv * DKv * Ev];  // Wk^T in fp16: [h][n][e]

// ---------------------------------------------------------------------------
// PTX helpers (sm_80-level only; tcgen05 is rejected by this harness target)
// ---------------------------------------------------------------------------
__device__ __forceinline__ uint32_t smem_u32(const void* p) {
    uint32_t a;
    asm("{ .reg .u64 t; cvta.to.shared.u64 t, %1; cvt.u32.u64 %0, t; }" : "=r"(a) : "l"(p));
    return a;
}
#define CP16(sm, gm, sz) \
    asm volatile("cp.async.cg.shared.global [%0], [%1], 16, %2;" ::"r"(sm), "l"(gm), "r"(sz) : "memory")
#define CP_COMMIT() asm volatile("cp.async.commit_group;" ::: "memory")
#define CP_WAIT1() asm volatile("cp.async.wait_group 1;" ::: "memory")
#define LDSM4(r0, r1, r2, r3, a)                                             \
    asm volatile("ldmatrix.sync.aligned.m8n8.x4.shared.b16 {%0,%1,%2,%3}, [%4];" \
                 : "=r"(r0), "=r"(r1), "=r"(r2), "=r"(r3) : "r"(a))

__device__ __forceinline__ void mma_f16(float* d, uint32_t a0, uint32_t a1, uint32_t a2,
                                        uint32_t a3, uint32_t b0, uint32_t b1) {
    asm volatile(
        "mma.sync.aligned.m16n8k16.row.col.f32.f16.f16.f32 "
        "{%0,%1,%2,%3}, {%4,%5,%6,%7}, {%8,%9}, {%0,%1,%2,%3};"
        : "+f"(d[0]), "+f"(d[1]), "+f"(d[2]), "+f"(d[3])
        : "r"(a0), "r"(a1), "r"(a2), "r"(a3), "r"(b0), "r"(b1));
}
__device__ __forceinline__ uint32_t sw128(uint32_t o) { return o ^ ((o >> 3) & 0x70); }

// ---------------------------------------------------------------------------
// Length read with dtype sniff (int64 declared, int32 in practice)
// ---------------------------------------------------------------------------
__device__ __forceinline__ int get_len(const int* __restrict__ L, int b) {
    bool is64 = (L[1] == 0);
    return is64 ? L[2 * b] : L[b];
}

// ---------------------------------------------------------------------------
// enc -> fp16 (round-to-nearest), clipped to ceil128(len) rows per batch.
// ---------------------------------------------------------------------------
__global__ __launch_bounds__(256) void enc16_kernel(const float* __restrict__ enc,
                                                    const int* __restrict__ lens) {
    size_t base = ((size_t)blockIdx.x * 256 + threadIdx.x) * 8;
    int t = (int)((base / Ev) % Tv);
    int b = (int)(base / ((size_t)Ev * Tv));
    int len = get_len(lens, b);
    if (t >= ((len + 127) & ~127)) return;
    float4 v0 = *(const float4*)(enc + base);
    float4 v1 = *(const float4*)(enc + base + 4);
    __half2 h[4];
    h[0] = __floats2half2_rn(v0.x, v0.y);
    h[1] = __floats2half2_rn(v0.z, v0.w);
    h[2] = __floats2half2_rn(v1.x, v1.y);
    h[3] = __floats2half2_rn(v1.z, v1.w);
    *(uint4*)(g_enc16 + base) = *(uint4*)h;
}

// ---------------------------------------------------------------------------
// wkT16[h][n][e] = fp16(Wk[h][e][n])
// ---------------------------------------------------------------------------
__global__ __launch_bounds__(256) void wkT16_kernel(const float* __restrict__ Wk) {
    __shared__ float tile[32][33];
    int e0 = blockIdx.x * 32, n0 = blockIdx.y * 32, h = blockIdx.z;
    int tx = threadIdx.x & 31, ty = threadIdx.x >> 5;
    for (int i = ty; i < 32; i += 8)
        tile[i][tx] = Wk[((size_t)h * Ev + e0 + i) * DKv + n0 + tx];
    __syncthreads();
    for (int i = ty; i < 32; i += 8)
        g_wkT16[((size_t)h * DKv + n0 + i) * Ev + e0 + tx] = __float2half_rn(tile[tx][i]);
}

// ---------------------------------------------------------------------------
// q[b,h,k] = tanh(dec_z[b,:]·Wq[h,:,k] + bq[h,k])
// 4 independent accumulators, 16-deep load batching (MLP ~16).
// ---------------------------------------------------------------------------
__global__ __launch_bounds__(128) void q_kernel(const float* __restrict__ dec_z,
                                                const float* __restrict__ Wq,
                                                const float* __restrict__ bq) {
    int h = blockIdx.x, b = blockIdx.y;
    int k = threadIdx.x;
    __shared__ float zs[Dv];
    for (int i = k; i < Dv; i += 128) zs[i] = dec_z[b * Dv + i];
    __syncthreads();
    const float* W = Wq + (size_t)h * Dv * DKv + k;
    float a[4] = {0.f, 0.f, 0.f, 0.f};
#pragma unroll 4
    for (int d = 0; d < Dv; d += 4) {
        a[0] += zs[d] * W[(size_t)d * DKv];
        a[1] += zs[d + 1] * W[(size_t)(d + 1) * DKv];
        a[2] += zs[d + 2] * W[(size_t)(d + 2) * DKv];
        a[3] += zs[d + 3] * W[(size_t)(d + 3) * DKv];
    }
    g_q[(b * Hv + h) * DKv + k] = tanhf(bq[h * DKv + k] + (a[0] + a[1]) + (a[2] + a[3]));
}

// ---------------------------------------------------------------------------
// e[b,h,t] = sum_n tanh( (enc@Wk[h])[t,n] ) * q[b,h,n]
// fp16 m16n8k16 GEMM: per CTA = (h, 128-t tile, b); t0 >= len tiles exit.
// 3-stage cp.async ring, precomputed swizzled addrs, ldmatrix.x4 fragments.
// ---------------------------------------------------------------------------
#define ECH 64                 // K halves per stage (128 B per row)
#define ENCH (Ev / ECH)        // 16 chunks
#define EST 16384              // one tile stage: 128 rows * 128 B
#define NSTG 3
#define OFF_QS (2 * NSTG * EST)          // 98304
#define OFF_RED (OFF_QS + 512)
#define E_SMEM (OFF_RED + 1024)          // 99840 (x2 CTAs fits 228KB)

__global__ __launch_bounds__(256, 2) void e_tc_kernel(float* __restrict__ ebuf,
                                                      const int* __restrict__ lens) {
    extern __shared__ __align__(16) char dsm[];
    float* qs = (float*)(dsm + OFF_QS);
    float* red = (float*)(dsm + OFF_RED);  // [2][128]

    int tid = threadIdx.x, wid = tid >> 5, lane = tid & 31;
    int h = blockIdx.x, tile = blockIdx.y, b = blockIdx.z;
    int t0 = tile * 128;
    int len = get_len(lens, b);
    if (t0 >= len) return;  // dead tile: softmax writes 0 over this range

    int wm = wid & 3, wn = wid >> 2;
    int lane4 = lane >> 2, laneq = lane & 3;

    if (tid < DKv) qs[tid] = g_q[(b * Hv + h) * DKv + tid];

    const __half* A = g_enc16 + (size_t)b * Tv * Ev;
    const __half* Wt = g_wkT16 + (size_t)h * DKv * Ev;

    uint32_t base = smem_u32(dsm);

    uint32_t swz[4];
    const __half* pA[4];
    const __half* pB[4];
    uint32_t szA[4];
#pragma unroll
    for (int r = 0; r < 4; r++) {
        int idx = r * 256 + tid;
        int row = idx >> 3, seg = idx & 7;
        swz[r] = sw128(row * 128 + seg * 16);
        int t = t0 + row;
        szA[r] = (t < Tv) ? 16u : 0u;
        pA[r] = A + (size_t)t * Ev + seg * 8;
        pB[r] = Wt + (size_t)row * Ev + seg * 8;
    }

    auto issue = [&](int c, int s) {
        int k0 = c * ECH;
        uint32_t bA = base + s * EST, bB = base + (NSTG + s) * EST;
#pragma unroll
        for (int r = 0; r < 4; r++) CP16(bA + swz[r], pA[r] + k0, szA[r]);
#pragma unroll
        for (int r = 0; r < 4; r++) CP16(bB + swz[r], pB[r] + k0, 16u);
        CP_COMMIT();
    };

    int rowAl = (lane & 7) + ((lane >> 3) & 1) * 8;
    int colAl = ((lane >> 4) & 1) * 16;
    int rowBl = (lane & 7) + ((lane >> 4) & 1) * 8;
    int colBl = ((lane >> 3) & 1) * 16;
    uint32_t aRow[2], aMask[2];
#pragma unroll
    for (int ms = 0; ms < 2; ms++) {
        int row = wm * 32 + ms * 16 + rowAl;
        aRow[ms] = row * 128;
        aMask[ms] = (row & 7) << 4;
    }
    uint32_t bRow[4], bMask[4];
#pragma unroll
    for (int pp = 0; pp < 4; pp++) {
        int row = wn * 64 + pp * 16 + rowBl;
        bRow[pp] = row * 128;
        bMask[pp] = (row & 7) << 4;
    }

    float d[2][8][4];
#pragma unroll
    for (int ms = 0; ms < 2; ms++)
#pragma unroll
        for (int ns = 0; ns < 8; ns++)
#pragma unroll
            for (int j = 0; j < 4; j++) d[ms][ns][j] = 0.f;

    issue(0, 0);
    issue(1, 1);

    for (int c = 0; c < ENCH; c++) {
        int s = c % NSTG;
        CP_WAIT1();
        __syncthreads();
        if (c + 2 < ENCH) issue(c + 2, (c + 2) % NSTG);
        uint32_t bA = base + s * EST, bB = base + (NSTG + s) * EST;
#pragma unroll
        for (int kk = 0; kk < 4; kk++) {
            uint32_t kb = kk * 32;
            uint32_t af[2][4];
#pragma unroll
            for (int ms = 0; ms < 2; ms++)
                LDSM4(af[ms][0], af[ms][1], af[ms][2], af[ms][3],
                      bA + aRow[ms] + (((uint32_t)colAl + kb) ^ aMask[ms]));
            uint32_t bf[8][2];
#pragma unroll
            for (int pp = 0; pp < 4; pp++)
                LDSM4(bf[2 * pp][0], bf[2 * pp][1], bf[2 * pp + 1][0], bf[2 * pp + 1][1],
                      bB + bRow[pp] + (((uint32_t)colBl + kb) ^ bMask[pp]));
#pragma unroll
            for (int ms = 0; ms < 2; ms++)
#pragma unroll
                for (int ns = 0; ns < 8; ns++)
                    mma_f16(d[ms][ns], af[ms][0], af[ms][1], af[ms][2], af[ms][3],
                            bf[ns][0], bf[ns][1]);
        }
    }

    // Epilogue: tanh + q-dot; reduce over cols (4 lanes) via shfl, warps via smem
#pragma unroll
    for (int ms = 0; ms < 2; ms++) {
        float pr0 = 0.f, pr1 = 0.f;
#pragma unroll
        for (int ns = 0; ns < 8; ns++) {
            int n0 = wn * 64 + ns * 8 + 2 * laneq;
            float q0 = qs[n0], q1 = qs[n0 + 1];
            pr0 += tanhf(d[ms][ns][0]) * q0 + tanhf(d[ms][ns][1]) * q1;
            pr1 += tanhf(d[ms][ns][2]) * q0 + tanhf(d[ms][ns][3]) * q1;
        }
#pragma unroll
        for (int o = 1; o < 4; o <<= 1) {
            pr0 += __shfl_xor_sync(0xffffffffu, pr0, o);
            pr1 += __shfl_xor_sync(0xffffffffu, pr1, o);
        }
        if (laneq == 0) {
            int r = wm * 32 + ms * 16 + lane4;
            red[wn * 128 + r] = pr0;
            red[wn * 128 + r + 8] = pr1;
        }
    }
    __syncthreads();
    if (tid < 128) {
        int t = t0 + tid;
        if (t < Tv)
            ebuf[(size_t)(b * Hv + h) * Tv + t] = red[tid] + red[128 + tid];
    }
}

// ---------------------------------------------------------------------------
// Masked softmax over T, in place. w = softmax(SCALING*e) on t<len, 0 else.
// ---------------------------------------------------------------------------
__global__ __launch_bounds__(256) void softmax_kernel(float* __restrict__ wbuf,
                                                      const int* __restrict__ lens) {
    int bh = blockIdx.x;
    int b = bh / Hv;
    int len = get_len(lens, b);
    int tid = threadIdx.x;
    __shared__ float s[Tv];
    __shared__ float red[16];
    float* row = wbuf + (size_t)bh * Tv;
    for (int t = tid; t < Tv; t += 256) s[t] = row[t];
    __syncthreads();

    float m = -1e30f;
    for (int t = tid; t < len; t += 256) m = fmaxf(m, s[t]);
#pragma unroll
    for (int o = 16; o; o >>= 1) m = fmaxf(m, __shfl_xor_sync(0xffffffffu, m, o));
    if ((tid & 31) == 0) red[tid >> 5] = m;
    __syncthreads();
    m = red[0];
#pragma unroll
    for (int i = 1; i < 8; i++) m = fmaxf(m, red[i]);
    float M = SCALING * m;

    float lsum = 0.f;
    for (int t = tid; t < len; t += 256) lsum += expf(SCALING * s[t] - M);
#pragma unroll
    for (int o = 16; o; o >>= 1) lsum += __shfl_xor_sync(0xffffffffu, lsum, o);
    if ((tid & 31) == 0) red[8 + (tid >> 5)] = lsum;
    __syncthreads();
    float total = 0.f;
#pragma unroll
    for (int i = 0; i < 8; i++) total += red[8 + i];
    float inv = 1.f / total;

    for (int t = tid; t < Tv; t += 256)
        row[t] = (t < len) ? expf(SCALING * s[t] - M) * inv : 0.f;
}

// ---------------------------------------------------------------------------
// u partials, vectorized (4 d per thread), unroll 4 over t for MLP.
// ---------------------------------------------------------------------------
__global__ __launch_bounds__(256) void u_kernel(const float* __restrict__ wbuf,
                                                const int* __restrict__ lens) {
    int tc = blockIdx.x, b = blockIdx.y;
    int d0 = threadIdx.x * 4;
    int len = get_len(lens, b);
    int t0 = tc * 128;
    float* up = g_up + (((size_t)tc * Bv + b) * Hv) * Ev + d0;
    if (t0 >= len) {
#pragma unroll
        for (int h = 0; h < Hv; h++)
            *(float4*)(up + (size_t)h * Ev) = make_float4(0.f, 0.f, 0.f, 0.f);
        return;
    }
    int tmax = min(min(128, Tv - t0), len - t0);
    __shared__ float ws[Hv][128];
#pragma unroll
    for (int r = 0; r < 4; r++) {
        int f = r * 256 + threadIdx.x;
        int h = f >> 7, tt = f & 127;
        int t = t0 + tt;
        ws[h][tt] = (t < Tv) ? wbuf[((size_t)(b * Hv + h)) * Tv + t] : 0.f;
    }
    __syncthreads();

    float acc[Hv][4];
#pragma unroll
    for (int h = 0; h < Hv; h++)
#pragma unroll
        for (int j = 0; j < 4; j++) acc[h][j] = 0.f;

    const __half* A = g_enc16 + (size_t)b * Tv * Ev + (size_t)t0 * Ev + d0;
#pragma unroll 4
    for (int tt = 0; tt < tmax; tt++) {
        uint2 raw = *(const uint2*)(A + (size_t)tt * Ev);
        float2 x01 = __half22float2(*(__half2*)&raw.x);
        float2 x23 = __half22float2(*(__half2*)&raw.y);
#pragma unroll
        for (int h = 0; h < Hv; h++) {
            float w = ws[h][tt];
            acc[h][0] += w * x01.x;
            acc[h][1] += w * x01.y;
            acc[h][2] += w * x23.x;
            acc[h][3] += w * x23.y;
        }
    }
#pragma unroll
    for (int h = 0; h < Hv; h++)
        *(float4*)(up + (size_t)h * Ev) =
            make_float4(acc[h][0], acc[h][1], acc[h][2], acc[h][3]);
}

// ---------------------------------------------------------------------------
// c[b,h,v] = u[b,h,:]·Wv[h,:,v]; 4 accumulators for MLP.
// ---------------------------------------------------------------------------
__global__ __launch_bounds__(128) void c_kernel(const float* __restrict__ Wv) {
    int h = blockIdx.x, b = blockIdx.y;
    int v = threadIdx.x;
    __shared__ float us[Ev];
    for (int i = v; i < Ev; i += 128) {
        float s0 = 0.f, s1 = 0.f;
#pragma unroll
        for (int tc = 0; tc < TCHUNK; tc += 2) {
            s0 += g_up[(((size_t)tc * Bv + b) * Hv + h) * Ev + i];
            s1 += g_up[(((size_t)(tc + 1) * Bv + b) * Hv + h) * Ev + i];
        }
        us[i] = s0 + s1;
    }
    __syncthreads();
    const float* W = Wv + (size_t)h * Ev * DVv + v;
    float a[4] = {0.f, 0.f, 0.f, 0.f};
#pragma unroll 4
    for (int d = 0; d < Ev; d += 4) {
        a[0] += us[d] * W[(size_t)d * DVv];
        a[1] += us[d + 1] * W[(size_t)(d + 1) * DVv];
        a[2] += us[d + 2] * W[(size_t)(d + 2) * DVv];
        a[3] += us[d + 3] * W[(size_t)(d + 3) * DVv];
    }
    g_c[(b * Hv + h) * DVv + v] = (a[0] + a[1]) + (a[2] + a[3]);
}

// ---------------------------------------------------------------------------
// out[b,e] = c_flat[b,:]·Wo[:,e]; 4 accumulators for MLP.
// ---------------------------------------------------------------------------
__global__ __launch_bounds__(256) void out_kernel(const float* __restrict__ Wo,
                                                  float* __restrict__ out) {
    int chunk = blockIdx.x, b = blockIdx.y;
    int e = chunk * 256 + threadIdx.x;
    __shared__ float cs[Hv * DVv];
    for (int i = threadIdx.x; i < Hv * DVv; i += 256) cs[i] = g_c[b * Hv * DVv + i];
    __syncthreads();
    float a[4] = {0.f, 0.f, 0.f, 0.f};
#pragma unroll 4
    for (int i = 0; i < Hv * DVv; i += 4) {
        a[0] += cs[i] * Wo[(size_t)i * Ev + e];
        a[1] += cs[i + 1] * Wo[(size_t)(i + 1) * Ev + e];
        a[2] += cs[i + 2] * Wo[(size_t)(i + 2) * Ev + e];
        a[3] += cs[i + 3] * Wo[(size_t)(i + 3) * Ev + e];
    }
    out[(size_t)b * Ev + e] = (a[0] + a[1]) + (a[2] + a[3]);
}

// ---------------------------------------------------------------------------
extern "C" void kernel_launch(void* const* d_in, const int* in_sizes, int n_in,
                              void* d_out, int out_size) {
    const float* enc   = (const float*)d_in[0];
    const int*   lens  = (const int*)d_in[1];
    const float* dec_z = (const float*)d_in[2];
    const float* Wq    = (const float*)d_in[3];
    const float* bq    = (const float*)d_in[4];
    const float* Wk    = (const float*)d_in[5];
    const float* Wv    = (const float*)d_in[6];
    const float* Wo    = (const float*)d_in[7];

    float* out  = (float*)d_out;   // (B,E)
    float* wbuf = out + Bv * Ev;   // (B,H,T): e logits, then w in place

    static int smem_set = 0;
    if (!smem_set) {
        cudaFuncSetAttribute(e_tc_kernel, cudaFuncAttributeMaxDynamicSharedMemorySize, E_SMEM);
        smem_set = 1;
    }

    enc16_kernel<<<(Bv * Tv * Ev) / (256 * 8), 256>>>(enc, lens);
    wkT16_kernel<<<dim3(Ev / 32, DKv / 32, Hv), 256>>>(Wk);
    q_kernel<<<dim3(Hv, Bv), 128>>>(dec_z, Wq, bq);
    e_tc_kernel<<<dim3(Hv, (Tv + 127) / 128, Bv), 256, E_SMEM>>>(wbuf, lens);
    softmax_kernel<<<Bv * Hv, 256>>>(wbuf, lens);
    u_kernel<<<dim3(TCHUNK, Bv), 256>>>(wbuf, lens);
    c_kernel<<<dim3(Hv, Bv), 128>>>(Wv);
    out_kernel<<<dim3(Ev / 256, Bv), 256>>>(Wo, out);
}